// round 11
// baseline (speedup 1.0000x reference)
#include <cuda_runtime.h>
#include <cuda_fp16.h>
#include <math.h>
#include <stdint.h>

#define BB 4
#define SS 2048
#define EE 1024
#define HH 16
#define DD 64
#define ND 1024
#define MM (BB*SS)   // 8192

// fp16 operands
__device__ __half g_Ah[MM*EE];          // GEMM A (X, later attention output)
__device__ __half g_Wh[4*ND*EE];        // weights transposed [z][n][k]
__device__ __half g_Qh[BB*HH*SS*DD];    // Q head-major (pre-scaled by 0.125*log2e)
__device__ __half g_Kh[BB*HH*SS*DD];    // K head-major
__device__ __half g_Vth[BB*HH*DD*SS];   // V transposed [bh][d][s]
// packed mask bits
__device__ uint32_t g_mbits[BB*SS*(SS/32)];

// ---------------------------------------------------------------------------
// PTX helpers (compute_103-safe)
// ---------------------------------------------------------------------------
__device__ __forceinline__ uint32_t smem_u32(const void* p) {
    return (uint32_t)__cvta_generic_to_shared(p);
}
__device__ __forceinline__ void ldsm4(uint32_t* r, uint32_t addr) {
    asm volatile("ldmatrix.sync.aligned.m8n8.x4.shared.b16 {%0,%1,%2,%3}, [%4];"
                 : "=r"(r[0]), "=r"(r[1]), "=r"(r[2]), "=r"(r[3]) : "r"(addr));
}
__device__ __forceinline__ void mma16816(float* c, const uint32_t* a, const uint32_t* b) {
    asm volatile("mma.sync.aligned.m16n8k16.row.col.f32.f16.f16.f32 "
                 "{%0,%1,%2,%3}, {%4,%5,%6,%7}, {%8,%9}, {%0,%1,%2,%3};"
                 : "+f"(c[0]), "+f"(c[1]), "+f"(c[2]), "+f"(c[3])
                 : "r"(a[0]), "r"(a[1]), "r"(a[2]), "r"(a[3]), "r"(b[0]), "r"(b[1]));
}
__device__ __forceinline__ void cp16(uint32_t dst, const void* src) {
    asm volatile("cp.async.cg.shared.global [%0], [%1], 16;" :: "r"(dst), "l"(src) : "memory");
}
__device__ __forceinline__ void cp_commit() {
    asm volatile("cp.async.commit_group;" ::: "memory");
}
template <int N>
__device__ __forceinline__ void cp_wait() {
    asm volatile("cp.async.wait_group %0;" :: "n"(N) : "memory");
}
__device__ __forceinline__ uint32_t packh(float a, float b) {
    __half2 t = __floats2half2_rn(a, b);
    return *reinterpret_cast<uint32_t*>(&t);
}
__device__ __forceinline__ uint32_t h2ex2(uint32_t x) {
    uint32_t y;
    asm volatile("ex2.approx.f16x2 %0, %1;" : "=r"(y) : "r"(x));
    return y;
}

// ---------------------------------------------------------------------------
// Prep kernel: X fp32 -> g_Ah fp16 (blocks [0,8192)), weights transpose+cvt
// (blocks [8192,12288)). Mask packing moved into the qkv GEMM launch.
// ---------------------------------------------------------------------------
#define PREP_X_BLOCKS 8192
#define PREP_W_BLOCKS 4096
#define PREP_BLOCKS (PREP_X_BLOCKS + PREP_W_BLOCKS)

__global__ __launch_bounds__(256) void prep_kernel(
    const float* __restrict__ X,
    const float* __restrict__ wQ, const float* __restrict__ wK,
    const float* __restrict__ wV, const float* __restrict__ wO)
{
    __shared__ float ts[32][33];
    const int bid = blockIdx.x;
    const int t = threadIdx.x;

    if (bid < PREP_X_BLOCKS) {
        int i4 = bid * 256 + t;
        float4 v = *(const float4*)(X + (size_t)i4 * 4);
        *(uint32_t*)(g_Ah + (size_t)i4 * 4)     = packh(v.x, v.y);
        *(uint32_t*)(g_Ah + (size_t)i4 * 4 + 2) = packh(v.z, v.w);
    } else {
        int id = bid - PREP_X_BLOCKS;          // 0..4095
        int wz = id >> 10;                      // 0..3
        int kb = (id >> 5) & 31;
        int nb = id & 31;
        const float* src = (wz == 0) ? wQ : (wz == 1) ? wK : (wz == 2) ? wV : wO;
        size_t dst0 = (size_t)wz * ND * EE;
        int tx = t & 31, ty = t >> 5;
        int k0 = kb * 32, n0 = nb * 32;
        #pragma unroll
        for (int i = 0; i < 4; ++i)
            ts[ty + i*8][tx] = src[(size_t)(k0 + ty + i*8) * ND + n0 + tx];
        __syncthreads();
        #pragma unroll
        for (int i = 0; i < 4; ++i) {
            float v = ts[tx][ty + i*8];
            g_Wh[dst0 + (size_t)(n0 + ty + i*8) * EE + k0 + tx] = __float2half(v);
        }
    }
}

// ---------------------------------------------------------------------------
// fp16 single-pass GEMM: CTA 128x128, BK=64, 8 warps, 3-stage cp.async.
// headmajor=1 (qkv launch, grid z=4): z=0 -> Qh (scaled 0.125*log2e),
//   z=1 -> Kh, z=2 -> Vth, z=3 -> mask bit-packing (overlapped on LSU/ALU).
// headmajor=0 (out-proj, grid z=1): fp32 row-major outr.
// ---------------------------------------------------------------------------
#define GBK 64
#define GROWB 144
#define GA_B (128*GROWB)          // 18432
#define GSTAGE (2*GA_B)           // 36864
#define GSMEM_TOTAL (3*GSTAGE)    // 110592

__global__ __launch_bounds__(256) void mma_gemm_kernel(
    int woff, const float* __restrict__ b0, const float* __restrict__ b1,
    const float* __restrict__ b2, int headmajor, float* __restrict__ outr,
    const int* __restrict__ mask)
{
    extern __shared__ char smc[];
    const uint32_t SB = smem_u32(smc);
    const int t = threadIdx.x;
    const int wid = t >> 5, lane = t & 31;
    const int z = blockIdx.z;

    if (z == 3) {
        // mask packing slice: 512 blocks x 1024 words each
        const int pid = blockIdx.y * gridDim.x + blockIdx.x;   // 0..511
        #pragma unroll 4
        for (int it = 0; it < 128; ++it) {
            int word = pid * 1024 + wid * 128 + it;            // < 524288
            int col = (word & 63) * 32 + lane;
            int row = word >> 6;
            int v = mask[(size_t)row * SS + col];
            uint32_t bits = __ballot_sync(0xffffffffu, v != 0);
            if (lane == 0) g_mbits[word] = bits;
        }
        return;
    }

    const int n0 = blockIdx.x * 128;
    const int m0 = blockIdx.y * 128;

    const __half* Wh = g_Wh + (size_t)(woff + z) * ND * EE;
    const float* bias = (z == 0) ? b0 : (z == 1) ? b1 : b2;

    const int wm = (wid & 3) * 32;
    const int wn = (wid >> 2) * 64;

    const int j = lane >> 3, r = lane & 7;
    const int rowA = wm + ((j & 1) << 3) + r;
    const int colA = (j >> 1) << 3;
    const int rowB = wn + ((j >> 1) << 3) + r;
    const int colB = (j & 1) << 3;

    float acc[2][8][4];
    #pragma unroll
    for (int mt = 0; mt < 2; ++mt)
        #pragma unroll
        for (int nt = 0; nt < 8; ++nt)
            #pragma unroll
            for (int q = 0; q < 4; ++q) acc[mt][nt][q] = 0.0f;

    auto load_stage = [&](int kt, int buf) {
        const int k0 = kt * GBK;
        const uint32_t bb = SB + buf * GSTAGE;
        #pragma unroll
        for (int i = 0; i < 4; ++i) {
            int idx = t + i * 256;
            int row = idx >> 3, q = idx & 7;
            cp16(bb + row*GROWB + q*16,        g_Ah + (size_t)(m0 + row) * EE + k0 + q*8);
            cp16(bb + GA_B + row*GROWB + q*16, Wh   + (size_t)(n0 + row) * EE + k0 + q*8);
        }
        cp_commit();
    };

    load_stage(0, 0);
    load_stage(1, 1);
    load_stage(2, 2);

    const int NSTAGE = EE / GBK;   // 16
    int buf = 0;
    for (int kt = 0; kt < NSTAGE; ++kt) {
        if (kt == NSTAGE - 1)      cp_wait<0>();
        else if (kt == NSTAGE - 2) cp_wait<1>();
        else                       cp_wait<2>();
        __syncthreads();
        const uint32_t bb = SB + buf * GSTAGE;

        #pragma unroll
        for (int ks = 0; ks < 4; ++ks) {
            uint32_t ah[2][4];
            #pragma unroll
            for (int mt = 0; mt < 2; ++mt) {
                uint32_t ad = bb + (uint32_t)(rowA + mt*16) * GROWB
                            + (uint32_t)(colA + ks*16) * 2;
                ldsm4(ah[mt], ad);
            }
            #pragma unroll
            for (int ntp = 0; ntp < 4; ++ntp) {
                uint32_t bh[4];
                uint32_t bd = bb + GA_B + (uint32_t)(rowB + ntp*16) * GROWB
                            + (uint32_t)(colB + ks*16) * 2;
                ldsm4(bh, bd);
                #pragma unroll
                for (int sub = 0; sub < 2; ++sub) {
                    uint32_t bb2[2] = {bh[sub*2], bh[sub*2+1]};
                    const int nt = ntp*2 + sub;
                    #pragma unroll
                    for (int mt = 0; mt < 2; ++mt)
                        mma16816(acc[mt][nt], ah[mt], bb2);
                }
            }
        }
        __syncthreads();
        if (kt + 3 < NSTAGE) load_stage(kt + 3, buf);
        buf = (buf == 2) ? 0 : buf + 1;
    }

    const int ncl = (lane & 3) << 1;
    const int mrw = lane >> 2;
    if (headmajor) {
        const int h = (n0 + wn) >> 6;
        if (z < 2) {
            const float sc = (z == 0) ? 0.125f * 1.4426950408889634f : 1.0f;
            __half* dh = z ? g_Kh : g_Qh;
            #pragma unroll
            for (int mt = 0; mt < 2; ++mt) {
                #pragma unroll
                for (int half_ = 0; half_ < 2; ++half_) {
                    int m = m0 + wm + mt*16 + mrw + half_*8;
                    int b_ = m >> 11, s_ = m & (SS - 1);
                    size_t rb = ((size_t)(b_*HH + h) * SS + s_) * DD;
                    #pragma unroll
                    for (int nt = 0; nt < 8; ++nt) {
                        int nn = nt*8 + ncl;
                        float2 bv = *(const float2*)(bias + n0 + wn + nn);
                        float vx = (acc[mt][nt][half_*2+0] + bv.x) * sc;
                        float vy = (acc[mt][nt][half_*2+1] + bv.y) * sc;
                        *(uint32_t*)(dh + rb + nn) = packh(vx, vy);
                    }
                }
            }
        } else {
            #pragma unroll
            for (int mt = 0; mt < 2; ++mt) {
                #pragma unroll
                for (int half_ = 0; half_ < 2; ++half_) {
                    int m = m0 + wm + mt*16 + mrw + half_*8;
                    int b_ = m >> 11, s_ = m & (SS - 1);
                    size_t base = (size_t)(b_*HH + h) * DD * SS;
                    #pragma unroll
                    for (int nt = 0; nt < 8; ++nt) {
                        int nn = nt*8 + ncl;
                        float2 bv = *(const float2*)(bias + n0 + wn + nn);
                        float vx = acc[mt][nt][half_*2+0] + bv.x;
                        float vy = acc[mt][nt][half_*2+1] + bv.y;
                        g_Vth[base + (size_t)nn     * SS + s_] = __float2half(vx);
                        g_Vth[base + (size_t)(nn+1) * SS + s_] = __float2half(vy);
                    }
                }
            }
        }
    } else {
        #pragma unroll
        for (int mt = 0; mt < 2; ++mt) {
            #pragma unroll
            for (int half_ = 0; half_ < 2; ++half_) {
                int m = m0 + wm + mt*16 + mrw + half_*8;
                float* op = outr + (size_t)m * ND + n0 + wn;
                #pragma unroll
                for (int nt = 0; nt < 8; ++nt) {
                    int nn = nt*8 + ncl;
                    float2 bv = *(const float2*)(bias + n0 + wn + nn);
                    float2 v;
                    v.x = acc[mt][nt][half_*2+0] + bv.x;
                    v.y = acc[mt][nt][half_*2+1] + bv.y;
                    *(float2*)(op + nn) = v;
                }
            }
        }
    }
}

// ---------------------------------------------------------------------------
// fp16 MMA flash attention, static-max softmax (unchanged from R10).
// ---------------------------------------------------------------------------
#define AROWB 144
#define AQ_B (128*AROWB)        // 18432
#define AK_B (64*AROWB)         // 9216
#define AOFF_KV 18432
#define AKV_STRIDE 18432
#define ATTN_SMEM (AOFF_KV + 3*AKV_STRIDE)   // 73728

__global__ __launch_bounds__(256, 2) void attn_mma_kernel()
{
    extern __shared__ char smc[];
    const uint32_t SB = smem_u32(smc);
    const int t = threadIdx.x, wid = t >> 5, lane = t & 31;
    const int bh = blockIdx.y, b_ = bh >> 4, h = bh & 15;
    const int q0 = blockIdx.x * 128;
    const int wm = wid * 16;

    const __half* Qh = g_Qh + (size_t)bh*SS*DD + (size_t)q0*DD;
    const __half* Kh = g_Kh + (size_t)bh*SS*DD;
    const __half* Vh = g_Vth + (size_t)bh*DD*SS;

    #pragma unroll
    for (int i = 0; i < 4; ++i) {
        int idx = t + i * 256;
        int row = idx >> 3, q = idx & 7;
        cp16(SB + row*AROWB + q*16, Qh + (size_t)row*DD + q*8);
    }
    auto load_kv = [&](int kt, int buf) {
        const int k0 = kt * 64;
        const uint32_t bb = SB + AOFF_KV + buf * AKV_STRIDE;
        #pragma unroll
        for (int i = 0; i < 2; ++i) {
            int idx = t + i * 256;
            int row = idx >> 3, q = idx & 7;
            cp16(bb + row*AROWB + q*16,        Kh + (size_t)(k0+row)*DD + q*8);
            cp16(bb + AK_B + row*AROWB + q*16, Vh + (size_t)row*SS + k0 + q*8);
        }
        cp_commit();
    };
    load_kv(0, 0);
    load_kv(1, 1);
    load_kv(2, 2);

    const int j = lane >> 3, r_ = lane & 7;
    const int rowA = wm + ((j & 1) << 3) + r_;
    const int colA = (j >> 1) << 3;
    const int rowB = ((j >> 1) << 3) + r_;
    const int colB = (j & 1) << 3;
    const int ncl2 = (lane & 3) << 1;
    const int mrw = lane >> 2;

    const uint32_t* mbp[2];
    #pragma unroll
    for (int hf = 0; hf < 2; ++hf)
        mbp[hf] = g_mbits + (size_t)(b_*SS + q0 + wm + hf*8 + mrw) * (SS/32);

    // hoist Q fragments
    uint32_t aq[4][4];
    cp_wait<2>();
    __syncthreads();
    #pragma unroll
    for (int ks = 0; ks < 4; ++ks)
        ldsm4(aq[ks], SB + (uint32_t)rowA*AROWB + (uint32_t)(colA + ks*16)*2);

    float o[8][4];
    float l_i[2] = {0.0f, 0.0f};
    #pragma unroll
    for (int dn = 0; dn < 8; ++dn)
        #pragma unroll
        for (int q = 0; q < 4; ++q) o[dn][q] = 0.0f;

    const int NKT = SS/64;
    int buf = 0;
    for (int kt = 0; kt < NKT; ++kt) {
        if (kt == NKT - 1)      cp_wait<0>();
        else if (kt == NKT - 2) cp_wait<1>();
        else                    cp_wait<2>();
        __syncthreads();
        const uint32_t bb = SB + AOFF_KV + buf * AKV_STRIDE;

        // prefetch mask words
        uint32_t mw[2][2];
        mw[0][0] = mbp[0][kt*2]; mw[0][1] = mbp[0][kt*2+1];
        mw[1][0] = mbp[1][kt*2]; mw[1][1] = mbp[1][kt*2+1];

        // S = Q K^T
        float s[8][4];
        #pragma unroll
        for (int jn = 0; jn < 8; ++jn)
            #pragma unroll
            for (int q = 0; q < 4; ++q) s[jn][q] = 0.0f;

        #pragma unroll
        for (int ks = 0; ks < 4; ++ks) {
            #pragma unroll
            for (int jnp = 0; jnp < 4; ++jnp) {
                uint32_t kh4[4];
                ldsm4(kh4, bb + (uint32_t)(rowB + jnp*16)*AROWB + (uint32_t)(colB + ks*16)*2);
                #pragma unroll
                for (int sub = 0; sub < 2; ++sub) {
                    uint32_t b2[2] = {kh4[sub*2], kh4[sub*2+1]};
                    mma16816(s[jnp*2 + sub], aq[ks], b2);
                }
            }
        }

        // mask -> -inf, p = exp2(s) in fp16 pairs
        uint32_t pfrag[8][2];
        #pragma unroll
        for (int jn = 0; jn < 8; ++jn) {
            const int sh = (jn*8 + ncl2) & 31;
            uint32_t w0 = mw[0][jn >> 2] >> sh;
            uint32_t w1 = mw[1][jn >> 2] >> sh;
            float s0 = (w0 & 1u) ? s[jn][0] : -1e30f;
            float s1 = (w0 & 2u) ? s[jn][1] : -1e30f;
            float s2 = (w1 & 1u) ? s[jn][2] : -1e30f;
            float s3 = (w1 & 2u) ? s[jn][3] : -1e30f;
            pfrag[jn][0] = h2ex2(packh(s0, s1));
            pfrag[jn][1] = h2ex2(packh(s2, s3));
        }

        // row-sum on fma pipe (fp32)
        #pragma unroll
        for (int hf = 0; hf < 2; ++hf) {
            float acc = 0.0f;
            #pragma unroll
            for (int jn = 0; jn < 8; ++jn) {
                float2 f = __half22float2(*reinterpret_cast<__half2*>(&pfrag[jn][hf]));
                acc += f.x + f.y;
            }
            acc += __shfl_xor_sync(0xffffffffu, acc, 1);
            acc += __shfl_xor_sync(0xffffffffu, acc, 2);
            l_i[hf] += acc;
        }

        // O += P V
        #pragma unroll
        for (int ks = 0; ks < 4; ++ks) {
            uint32_t pah[4] = {pfrag[2*ks][0], pfrag[2*ks][1],
                               pfrag[2*ks+1][0], pfrag[2*ks+1][1]};
            #pragma unroll
            for (int dnp = 0; dnp < 4; ++dnp) {
                uint32_t vh4[4];
                ldsm4(vh4, bb + AK_B + (uint32_t)(rowB + dnp*16)*AROWB
                           + (uint32_t)(colB + ks*16)*2);
                #pragma unroll
                for (int sub = 0; sub < 2; ++sub) {
                    uint32_t v2[2] = {vh4[sub*2], vh4[sub*2+1]};
                    mma16816(o[dnp*2 + sub], pah, v2);
                }
            }
        }

        __syncthreads();
        if (kt + 3 < NKT) load_kv(kt + 3, buf);
        buf = (buf == 2) ? 0 : buf + 1;
    }

    // normalize + write fp16 to out-proj A buffer [m][h*64+d]
    #pragma unroll
    for (int hf = 0; hf < 2; ++hf) {
        const int q = q0 + wm + hf*8 + mrw;
        const float inv = 1.0f / l_i[hf];
        size_t base = ((size_t)b_*SS + q) * ND + h*64;
        #pragma unroll
        for (int dn = 0; dn < 8; ++dn) {
            int d0 = dn*8 + ncl2;
            *(uint32_t*)(g_Ah + base + d0) =
                packh(o[dn][hf*2] * inv, o[dn][hf*2+1] * inv);
        }
    }
}

extern "C" void kernel_launch(void* const* d_in, const int* in_sizes, int n_in,
                              void* d_out, int out_size)
{
    const float* X    = (const float*)d_in[0];
    const int*   mask = (const int*)  d_in[1];
    const float* wQ   = (const float*)d_in[2];
    const float* bQ   = (const float*)d_in[3];
    const float* wK   = (const float*)d_in[4];
    const float* bK   = (const float*)d_in[5];
    const float* wV   = (const float*)d_in[6];
    const float* bV   = (const float*)d_in[7];
    const float* wO   = (const float*)d_in[8];
    const float* bO   = (const float*)d_in[9];
    float* out = (float*)d_out;

    cudaFuncSetAttribute(mma_gemm_kernel, cudaFuncAttributeMaxDynamicSharedMemorySize, GSMEM_TOTAL);
    cudaFuncSetAttribute(attn_mma_kernel, cudaFuncAttributeMaxDynamicSharedMemorySize, ATTN_SMEM);

    prep_kernel<<<PREP_BLOCKS, 256>>>(X, wQ, wK, wV, wO);
    // z=0..2: Q/K/V projections; z=3: mask bit-packing (independent, overlapped)
    mma_gemm_kernel<<<dim3(8, 64, 4), 256, GSMEM_TOTAL>>>(0, bQ, bK, bV, 1, nullptr, mask);
    attn_mma_kernel<<<dim3(16, 64), 256, ATTN_SMEM>>>();
    mma_gemm_kernel<<<dim3(8, 64, 1), 256, GSMEM_TOTAL>>>(3, bO, bO, bO, 0, out, nullptr);
}

// round 12
// speedup vs baseline: 1.5442x; 1.5442x over previous
#include <cuda_runtime.h>
#include <cuda_fp16.h>
#include <math.h>
#include <stdint.h>

#define BB 4
#define SS 2048
#define EE 1024
#define HH 16
#define DD 64
#define ND 1024
#define MM (BB*SS)   // 8192

// fp16 operands
__device__ __half g_Ah[MM*EE];          // GEMM A (X, later attention output)
__device__ __half g_Wh[4*ND*EE];        // weights transposed [z][n][k]
__device__ __half g_Qh[BB*HH*SS*DD];    // Q head-major (pre-scaled by 0.125*log2e)
__device__ __half g_Kh[BB*HH*SS*DD];    // K head-major
__device__ __half g_Vth[BB*HH*DD*SS];   // V transposed [bh][d][s]
// packed mask bits
__device__ uint32_t g_mbits[BB*SS*(SS/32)];

// ---------------------------------------------------------------------------
// PTX helpers (compute_103-safe)
// ---------------------------------------------------------------------------
__device__ __forceinline__ uint32_t smem_u32(const void* p) {
    return (uint32_t)__cvta_generic_to_shared(p);
}
__device__ __forceinline__ void ldsm4(uint32_t* r, uint32_t addr) {
    asm volatile("ldmatrix.sync.aligned.m8n8.x4.shared.b16 {%0,%1,%2,%3}, [%4];"
                 : "=r"(r[0]), "=r"(r[1]), "=r"(r[2]), "=r"(r[3]) : "r"(addr));
}
__device__ __forceinline__ void mma16816(float* c, const uint32_t* a, const uint32_t* b) {
    asm volatile("mma.sync.aligned.m16n8k16.row.col.f32.f16.f16.f32 "
                 "{%0,%1,%2,%3}, {%4,%5,%6,%7}, {%8,%9}, {%0,%1,%2,%3};"
                 : "+f"(c[0]), "+f"(c[1]), "+f"(c[2]), "+f"(c[3])
                 : "r"(a[0]), "r"(a[1]), "r"(a[2]), "r"(a[3]), "r"(b[0]), "r"(b[1]));
}
__device__ __forceinline__ void cp16(uint32_t dst, const void* src) {
    asm volatile("cp.async.cg.shared.global [%0], [%1], 16;" :: "r"(dst), "l"(src) : "memory");
}
__device__ __forceinline__ void cp_commit() {
    asm volatile("cp.async.commit_group;" ::: "memory");
}
template <int N>
__device__ __forceinline__ void cp_wait() {
    asm volatile("cp.async.wait_group %0;" :: "n"(N) : "memory");
}
__device__ __forceinline__ uint32_t packh(float a, float b) {
    __half2 t = __floats2half2_rn(a, b);
    return *reinterpret_cast<uint32_t*>(&t);
}
__device__ __forceinline__ uint32_t h2ex2(uint32_t x) {
    uint32_t y;
    asm volatile("ex2.approx.f16x2 %0, %1;" : "=r"(y) : "r"(x));
    return y;
}

// ---------------------------------------------------------------------------
// Fused prep kernel: one launch does cvt_x + cvt_w + pack_mask by block range.
//   blocks [0, 8192)            : X fp32 -> g_Ah fp16
//   blocks [8192, 8192+4096)    : weights fp32 -> g_Wh fp16 transposed
//   blocks [12288, 12288+16384) : mask int32 -> g_mbits bitmask
// ---------------------------------------------------------------------------
#define PREP_X_BLOCKS 8192
#define PREP_W_BLOCKS 4096
#define PREP_M_BLOCKS 16384
#define PREP_BLOCKS (PREP_X_BLOCKS + PREP_W_BLOCKS + PREP_M_BLOCKS)

__global__ __launch_bounds__(256) void prep_kernel(
    const float* __restrict__ X, const int* __restrict__ mask,
    const float* __restrict__ wQ, const float* __restrict__ wK,
    const float* __restrict__ wV, const float* __restrict__ wO)
{
    __shared__ float ts[32][33];
    const int bid = blockIdx.x;
    const int t = threadIdx.x;

    if (bid < PREP_X_BLOCKS) {
        int i4 = bid * 256 + t;
        float4 v = *(const float4*)(X + (size_t)i4 * 4);
        *(uint32_t*)(g_Ah + (size_t)i4 * 4)     = packh(v.x, v.y);
        *(uint32_t*)(g_Ah + (size_t)i4 * 4 + 2) = packh(v.z, v.w);
    } else if (bid < PREP_X_BLOCKS + PREP_W_BLOCKS) {
        int id = bid - PREP_X_BLOCKS;          // 0..4095
        int wz = id >> 10;                      // 0..3
        int kb = (id >> 5) & 31;
        int nb = id & 31;
        const float* src = (wz == 0) ? wQ : (wz == 1) ? wK : (wz == 2) ? wV : wO;
        size_t dst0 = (size_t)wz * ND * EE;
        int tx = t & 31, ty = t >> 5;
        int k0 = kb * 32, n0 = nb * 32;
        #pragma unroll
        for (int i = 0; i < 4; ++i)
            ts[ty + i*8][tx] = src[(size_t)(k0 + ty + i*8) * ND + n0 + tx];
        __syncthreads();
        #pragma unroll
        for (int i = 0; i < 4; ++i) {
            float v = ts[tx][ty + i*8];
            g_Wh[dst0 + (size_t)(n0 + ty + i*8) * EE + k0 + tx] = __float2half(v);
        }
    } else {
        int pid = bid - PREP_X_BLOCKS - PREP_W_BLOCKS;   // 0..16383
        int wid = t >> 5, lane = t & 31;
        #pragma unroll
        for (int i = 0; i < 4; ++i) {
            int word = pid * 32 + wid * 4 + i;           // < 524288
            int col = (word & 63) * 32 + lane;
            int row = word >> 6;
            int v = mask[(size_t)row * SS + col];
            uint32_t bits = __ballot_sync(0xffffffffu, v != 0);
            if (lane == 0) g_mbits[word] = bits;
        }
    }
}

// ---------------------------------------------------------------------------
// fp16 single-pass GEMM: CTA 128x128, BK=64, 8 warps, 3-stage cp.async.
// headmajor=1: z=0 -> Qh (scaled 0.125*log2e), z=1 -> Kh, z=2 -> Vth.
// headmajor=0: fp32 row-major outr.
// ---------------------------------------------------------------------------
#define GBK 64
#define GROWB 144
#define GA_B (128*GROWB)          // 18432
#define GSTAGE (2*GA_B)           // 36864
#define GSMEM_TOTAL (3*GSTAGE)    // 110592

__global__ __launch_bounds__(256) void mma_gemm_kernel(
    int woff, const float* __restrict__ b0, const float* __restrict__ b1,
    const float* __restrict__ b2, int headmajor, float* __restrict__ outr)
{
    extern __shared__ char smc[];
    const uint32_t SB = smem_u32(smc);
    const int t = threadIdx.x;
    const int wid = t >> 5, lane = t & 31;
    const int z = blockIdx.z;
    const int n0 = blockIdx.x * 128;
    const int m0 = blockIdx.y * 128;

    const __half* Wh = g_Wh + (size_t)(woff + z) * ND * EE;
    const float* bias = (z == 0) ? b0 : (z == 1) ? b1 : b2;

    const int wm = (wid & 3) * 32;
    const int wn = (wid >> 2) * 64;

    const int j = lane >> 3, r = lane & 7;
    const int rowA = wm + ((j & 1) << 3) + r;
    const int colA = (j >> 1) << 3;
    const int rowB = wn + ((j >> 1) << 3) + r;
    const int colB = (j & 1) << 3;

    float acc[2][8][4];
    #pragma unroll
    for (int mt = 0; mt < 2; ++mt)
        #pragma unroll
        for (int nt = 0; nt < 8; ++nt)
            #pragma unroll
            for (int q = 0; q < 4; ++q) acc[mt][nt][q] = 0.0f;

    auto load_stage = [&](int kt, int buf) {
        const int k0 = kt * GBK;
        const uint32_t bb = SB + buf * GSTAGE;
        #pragma unroll
        for (int i = 0; i < 4; ++i) {
            int idx = t + i * 256;
            int row = idx >> 3, q = idx & 7;
            cp16(bb + row*GROWB + q*16,        g_Ah + (size_t)(m0 + row) * EE + k0 + q*8);
            cp16(bb + GA_B + row*GROWB + q*16, Wh   + (size_t)(n0 + row) * EE + k0 + q*8);
        }
        cp_commit();
    };

    load_stage(0, 0);
    load_stage(1, 1);
    load_stage(2, 2);

    const int NSTAGE = EE / GBK;   // 16
    int buf = 0;
    for (int kt = 0; kt < NSTAGE; ++kt) {
        if (kt == NSTAGE - 1)      cp_wait<0>();
        else if (kt == NSTAGE - 2) cp_wait<1>();
        else                       cp_wait<2>();
        __syncthreads();
        const uint32_t bb = SB + buf * GSTAGE;

        #pragma unroll
        for (int ks = 0; ks < 4; ++ks) {
            uint32_t ah[2][4];
            #pragma unroll
            for (int mt = 0; mt < 2; ++mt) {
                uint32_t ad = bb + (uint32_t)(rowA + mt*16) * GROWB
                            + (uint32_t)(colA + ks*16) * 2;
                ldsm4(ah[mt], ad);
            }
            #pragma unroll
            for (int ntp = 0; ntp < 4; ++ntp) {
                uint32_t bh[4];
                uint32_t bd = bb + GA_B + (uint32_t)(rowB + ntp*16) * GROWB
                            + (uint32_t)(colB + ks*16) * 2;
                ldsm4(bh, bd);
                #pragma unroll
                for (int sub = 0; sub < 2; ++sub) {
                    uint32_t bb2[2] = {bh[sub*2], bh[sub*2+1]};
                    const int nt = ntp*2 + sub;
                    #pragma unroll
                    for (int mt = 0; mt < 2; ++mt)
                        mma16816(acc[mt][nt], ah[mt], bb2);
                }
            }
        }
        __syncthreads();
        if (kt + 3 < NSTAGE) load_stage(kt + 3, buf);
        buf = (buf == 2) ? 0 : buf + 1;
    }

    const int ncl = (lane & 3) << 1;
    const int mrw = lane >> 2;
    if (headmajor) {
        const int h = (n0 + wn) >> 6;
        if (z < 2) {
            const float sc = (z == 0) ? 0.125f * 1.4426950408889634f : 1.0f;
            __half* dh = z ? g_Kh : g_Qh;
            #pragma unroll
            for (int mt = 0; mt < 2; ++mt) {
                #pragma unroll
                for (int half_ = 0; half_ < 2; ++half_) {
                    int m = m0 + wm + mt*16 + mrw + half_*8;
                    int b_ = m >> 11, s_ = m & (SS - 1);
                    size_t rb = ((size_t)(b_*HH + h) * SS + s_) * DD;
                    #pragma unroll
                    for (int nt = 0; nt < 8; ++nt) {
                        int nn = nt*8 + ncl;
                        float2 bv = *(const float2*)(bias + n0 + wn + nn);
                        float vx = (acc[mt][nt][half_*2+0] + bv.x) * sc;
                        float vy = (acc[mt][nt][half_*2+1] + bv.y) * sc;
                        *(uint32_t*)(dh + rb + nn) = packh(vx, vy);
                    }
                }
            }
        } else {
            #pragma unroll
            for (int mt = 0; mt < 2; ++mt) {
                #pragma unroll
                for (int half_ = 0; half_ < 2; ++half_) {
                    int m = m0 + wm + mt*16 + mrw + half_*8;
                    int b_ = m >> 11, s_ = m & (SS - 1);
                    size_t base = (size_t)(b_*HH + h) * DD * SS;
                    #pragma unroll
                    for (int nt = 0; nt < 8; ++nt) {
                        int nn = nt*8 + ncl;
                        float2 bv = *(const float2*)(bias + n0 + wn + nn);
                        float vx = acc[mt][nt][half_*2+0] + bv.x;
                        float vy = acc[mt][nt][half_*2+1] + bv.y;
                        g_Vth[base + (size_t)nn     * SS + s_] = __float2half(vx);
                        g_Vth[base + (size_t)(nn+1) * SS + s_] = __float2half(vy);
                    }
                }
            }
        }
    } else {
        #pragma unroll
        for (int mt = 0; mt < 2; ++mt) {
            #pragma unroll
            for (int half_ = 0; half_ < 2; ++half_) {
                int m = m0 + wm + mt*16 + mrw + half_*8;
                float* op = outr + (size_t)m * ND + n0 + wn;
                #pragma unroll
                for (int nt = 0; nt < 8; ++nt) {
                    int nn = nt*8 + ncl;
                    float2 bv = *(const float2*)(bias + n0 + wn + nn);
                    float2 v;
                    v.x = acc[mt][nt][half_*2+0] + bv.x;
                    v.y = acc[mt][nt][half_*2+1] + bv.y;
                    *(float2*)(op + nn) = v;
                }
            }
        }
    }
}

// ---------------------------------------------------------------------------
// fp16 MMA flash attention, static-max softmax. Row-sum via fp32 scalar adds
// on the idle fma pipe. (bh, 128-q tile); 256 thr, 8 warps (warp m=16);
// k-tiles of 64, 3-stage KV pipeline, Q fragments hoisted.
// ---------------------------------------------------------------------------
#define AROWB 144
#define AQ_B (128*AROWB)        // 18432
#define AK_B (64*AROWB)         // 9216
#define AOFF_KV 18432
#define AKV_STRIDE 18432
#define ATTN_SMEM (AOFF_KV + 3*AKV_STRIDE)   // 73728

__global__ __launch_bounds__(256, 2) void attn_mma_kernel()
{
    extern __shared__ char smc[];
    const uint32_t SB = smem_u32(smc);
    const int t = threadIdx.x, wid = t >> 5, lane = t & 31;
    const int bh = blockIdx.y, b_ = bh >> 4, h = bh & 15;
    const int q0 = blockIdx.x * 128;
    const int wm = wid * 16;

    const __half* Qh = g_Qh + (size_t)bh*SS*DD + (size_t)q0*DD;
    const __half* Kh = g_Kh + (size_t)bh*SS*DD;
    const __half* Vh = g_Vth + (size_t)bh*DD*SS;

    #pragma unroll
    for (int i = 0; i < 4; ++i) {
        int idx = t + i * 256;
        int row = idx >> 3, q = idx & 7;
        cp16(SB + row*AROWB + q*16, Qh + (size_t)row*DD + q*8);
    }
    auto load_kv = [&](int kt, int buf) {
        const int k0 = kt * 64;
        const uint32_t bb = SB + AOFF_KV + buf * AKV_STRIDE;
        #pragma unroll
        for (int i = 0; i < 2; ++i) {
            int idx = t + i * 256;
            int row = idx >> 3, q = idx & 7;
            cp16(bb + row*AROWB + q*16,        Kh + (size_t)(k0+row)*DD + q*8);
            cp16(bb + AK_B + row*AROWB + q*16, Vh + (size_t)row*SS + k0 + q*8);
        }
        cp_commit();
    };
    load_kv(0, 0);
    load_kv(1, 1);
    load_kv(2, 2);

    const int j = lane >> 3, r_ = lane & 7;
    const int rowA = wm + ((j & 1) << 3) + r_;
    const int colA = (j >> 1) << 3;
    const int rowB = ((j >> 1) << 3) + r_;
    const int colB = (j & 1) << 3;
    const int ncl2 = (lane & 3) << 1;
    const int mrw = lane >> 2;

    const uint32_t* mbp[2];
    #pragma unroll
    for (int hf = 0; hf < 2; ++hf)
        mbp[hf] = g_mbits + (size_t)(b_*SS + q0 + wm + hf*8 + mrw) * (SS/32);

    // hoist Q fragments
    uint32_t aq[4][4];
    cp_wait<2>();
    __syncthreads();
    #pragma unroll
    for (int ks = 0; ks < 4; ++ks)
        ldsm4(aq[ks], SB + (uint32_t)rowA*AROWB + (uint32_t)(colA + ks*16)*2);

    float o[8][4];
    float l_i[2] = {0.0f, 0.0f};
    #pragma unroll
    for (int dn = 0; dn < 8; ++dn)
        #pragma unroll
        for (int q = 0; q < 4; ++q) o[dn][q] = 0.0f;

    const int NKT = SS/64;
    int buf = 0;
    for (int kt = 0; kt < NKT; ++kt) {
        if (kt == NKT - 1)      cp_wait<0>();
        else if (kt == NKT - 2) cp_wait<1>();
        else                    cp_wait<2>();
        __syncthreads();
        const uint32_t bb = SB + AOFF_KV + buf * AKV_STRIDE;

        // prefetch mask words
        uint32_t mw[2][2];
        mw[0][0] = mbp[0][kt*2]; mw[0][1] = mbp[0][kt*2+1];
        mw[1][0] = mbp[1][kt*2]; mw[1][1] = mbp[1][kt*2+1];

        // S = Q K^T
        float s[8][4];
        #pragma unroll
        for (int jn = 0; jn < 8; ++jn)
            #pragma unroll
            for (int q = 0; q < 4; ++q) s[jn][q] = 0.0f;

        #pragma unroll
        for (int ks = 0; ks < 4; ++ks) {
            #pragma unroll
            for (int jnp = 0; jnp < 4; ++jnp) {
                uint32_t kh4[4];
                ldsm4(kh4, bb + (uint32_t)(rowB + jnp*16)*AROWB + (uint32_t)(colB + ks*16)*2);
                #pragma unroll
                for (int sub = 0; sub < 2; ++sub) {
                    uint32_t b2[2] = {kh4[sub*2], kh4[sub*2+1]};
                    mma16816(s[jnp*2 + sub], aq[ks], b2);
                }
            }
        }

        // mask -> -inf, p = exp2(s) in fp16 pairs
        uint32_t pfrag[8][2];
        #pragma unroll
        for (int jn = 0; jn < 8; ++jn) {
            const int sh = (jn*8 + ncl2) & 31;
            uint32_t w0 = mw[0][jn >> 2] >> sh;
            uint32_t w1 = mw[1][jn >> 2] >> sh;
            float s0 = (w0 & 1u) ? s[jn][0] : -1e30f;
            float s1 = (w0 & 2u) ? s[jn][1] : -1e30f;
            float s2 = (w1 & 1u) ? s[jn][2] : -1e30f;
            float s3 = (w1 & 2u) ? s[jn][3] : -1e30f;
            pfrag[jn][0] = h2ex2(packh(s0, s1));
            pfrag[jn][1] = h2ex2(packh(s2, s3));
        }

        // row-sum on fma pipe (fp32)
        #pragma unroll
        for (int hf = 0; hf < 2; ++hf) {
            float acc = 0.0f;
            #pragma unroll
            for (int jn = 0; jn < 8; ++jn) {
                float2 f = __half22float2(*reinterpret_cast<__half2*>(&pfrag[jn][hf]));
                acc += f.x + f.y;
            }
            acc += __shfl_xor_sync(0xffffffffu, acc, 1);
            acc += __shfl_xor_sync(0xffffffffu, acc, 2);
            l_i[hf] += acc;
        }

        // O += P V
        #pragma unroll
        for (int ks = 0; ks < 4; ++ks) {
            uint32_t pah[4] = {pfrag[2*ks][0], pfrag[2*ks][1],
                               pfrag[2*ks+1][0], pfrag[2*ks+1][1]};
            #pragma unroll
            for (int dnp = 0; dnp < 4; ++dnp) {
                uint32_t vh4[4];
                ldsm4(vh4, bb + AK_B + (uint32_t)(rowB + dnp*16)*AROWB
                           + (uint32_t)(colB + ks*16)*2);
                #pragma unroll
                for (int sub = 0; sub < 2; ++sub) {
                    uint32_t v2[2] = {vh4[sub*2], vh4[sub*2+1]};
                    mma16816(o[dnp*2 + sub], pah, v2);
                }
            }
        }

        __syncthreads();
        if (kt + 3 < NKT) load_kv(kt + 3, buf);
        buf = (buf == 2) ? 0 : buf + 1;
    }

    // normalize + write fp16 to out-proj A buffer [m][h*64+d]
    #pragma unroll
    for (int hf = 0; hf < 2; ++hf) {
        const int q = q0 + wm + hf*8 + mrw;
        const float inv = 1.0f / l_i[hf];
        size_t base = ((size_t)b_*SS + q) * ND + h*64;
        #pragma unroll
        for (int dn = 0; dn < 8; ++dn) {
            int d0 = dn*8 + ncl2;
            *(uint32_t*)(g_Ah + base + d0) =
                packh(o[dn][hf*2] * inv, o[dn][hf*2+1] * inv);
        }
    }
}

extern "C" void kernel_launch(void* const* d_in, const int* in_sizes, int n_in,
                              void* d_out, int out_size)
{
    const float* X    = (const float*)d_in[0];
    const int*   mask = (const int*)  d_in[1];
    const float* wQ   = (const float*)d_in[2];
    const float* bQ   = (const float*)d_in[3];
    const float* wK   = (const float*)d_in[4];
    const float* bK   = (const float*)d_in[5];
    const float* wV   = (const float*)d_in[6];
    const float* bV   = (const float*)d_in[7];
    const float* wO   = (const float*)d_in[8];
    const float* bO   = (const float*)d_in[9];
    float* out = (float*)d_out;

    cudaFuncSetAttribute(mma_gemm_kernel, cudaFuncAttributeMaxDynamicSharedMemorySize, GSMEM_TOTAL);
    cudaFuncSetAttribute(attn_mma_kernel, cudaFuncAttributeMaxDynamicSharedMemorySize, ATTN_SMEM);

    prep_kernel<<<PREP_BLOCKS, 256>>>(X, mask, wQ, wK, wV, wO);
    mma_gemm_kernel<<<dim3(8, 64, 3), 256, GSMEM_TOTAL>>>(0, bQ, bK, bV, 1, nullptr);
    attn_mma_kernel<<<dim3(16, 64), 256, ATTN_SMEM>>>();
    mma_gemm_kernel<<<dim3(8, 64, 1), 256, GSMEM_TOTAL>>>(3, bO, bO, bO, 0, out);
}

// round 13
// speedup vs baseline: 1.5528x; 1.0055x over previous
#include <cuda_runtime.h>
#include <cuda_fp16.h>
#include <math.h>
#include <stdint.h>

#define BB 4
#define SS 2048
#define EE 1024
#define HH 16
#define DD 64
#define ND 1024
#define MM (BB*SS)   // 8192

// fp16 operands
__device__ __half g_Ah[MM*EE];          // GEMM A (X, later attention output)
__device__ __half g_Wh[4*ND*EE];        // weights transposed [z][n][k]
__device__ __half g_Qh[BB*HH*SS*DD];    // Q head-major (pre-scaled by 0.125*log2e)
__device__ __half g_Kh[BB*HH*SS*DD];    // K head-major
__device__ __half g_Vth[BB*HH*DD*SS];   // V transposed [bh][d][s]
// packed mask bits
__device__ uint32_t g_mbits[BB*SS*(SS/32)];

// ---------------------------------------------------------------------------
// PTX helpers (compute_103-safe)
// ---------------------------------------------------------------------------
__device__ __forceinline__ uint32_t smem_u32(const void* p) {
    return (uint32_t)__cvta_generic_to_shared(p);
}
__device__ __forceinline__ void ldsm4(uint32_t* r, uint32_t addr) {
    asm volatile("ldmatrix.sync.aligned.m8n8.x4.shared.b16 {%0,%1,%2,%3}, [%4];"
                 : "=r"(r[0]), "=r"(r[1]), "=r"(r[2]), "=r"(r[3]) : "r"(addr));
}
__device__ __forceinline__ void mma16816(float* c, const uint32_t* a, const uint32_t* b) {
    asm volatile("mma.sync.aligned.m16n8k16.row.col.f32.f16.f16.f32 "
                 "{%0,%1,%2,%3}, {%4,%5,%6,%7}, {%8,%9}, {%0,%1,%2,%3};"
                 : "+f"(c[0]), "+f"(c[1]), "+f"(c[2]), "+f"(c[3])
                 : "r"(a[0]), "r"(a[1]), "r"(a[2]), "r"(a[3]), "r"(b[0]), "r"(b[1]));
}
__device__ __forceinline__ void cp16(uint32_t dst, const void* src) {
    asm volatile("cp.async.cg.shared.global [%0], [%1], 16;" :: "r"(dst), "l"(src) : "memory");
}
__device__ __forceinline__ void cp_commit() {
    asm volatile("cp.async.commit_group;" ::: "memory");
}
template <int N>
__device__ __forceinline__ void cp_wait() {
    asm volatile("cp.async.wait_group %0;" :: "n"(N) : "memory");
}
__device__ __forceinline__ uint32_t packh(float a, float b) {
    __half2 t = __floats2half2_rn(a, b);
    return *reinterpret_cast<uint32_t*>(&t);
}
__device__ __forceinline__ uint32_t h2ex2(uint32_t x) {
    uint32_t y;
    asm volatile("ex2.approx.f16x2 %0, %1;" : "=r"(y) : "r"(x));
    return y;
}

// ---------------------------------------------------------------------------
// Fused prep kernel, MLP-4 restructure:
//   blocks [0, 2048)      : X fp32 -> g_Ah fp16, 4 float4 loads per thread
//   blocks [2048, 6144)   : weights fp32 -> g_Wh fp16 transposed (smem)
//   blocks [6144, 8192)   : mask int32 -> g_mbits, 4-word load batches
// ---------------------------------------------------------------------------
#define PREP_X_BLOCKS 2048
#define PREP_W_BLOCKS 4096
#define PREP_M_BLOCKS 2048
#define PREP_BLOCKS (PREP_X_BLOCKS + PREP_W_BLOCKS + PREP_M_BLOCKS)

__global__ __launch_bounds__(256) void prep_kernel(
    const float* __restrict__ X, const int* __restrict__ mask,
    const float* __restrict__ wQ, const float* __restrict__ wK,
    const float* __restrict__ wV, const float* __restrict__ wO)
{
    __shared__ float ts[32][33];
    const int bid = blockIdx.x;
    const int t = threadIdx.x;

    if (bid < PREP_X_BLOCKS) {
        // 4 float4 quads per thread, batched loads (MLP=4)
        float4 v[4];
        int i4b = bid * 1024 + t;
        #pragma unroll
        for (int i = 0; i < 4; ++i)
            v[i] = *(const float4*)(X + (size_t)(i4b + i*256) * 4);
        #pragma unroll
        for (int i = 0; i < 4; ++i) {
            size_t o = (size_t)(i4b + i*256) * 4;
            *(uint32_t*)(g_Ah + o)     = packh(v[i].x, v[i].y);
            *(uint32_t*)(g_Ah + o + 2) = packh(v[i].z, v[i].w);
        }
    } else if (bid < PREP_X_BLOCKS + PREP_W_BLOCKS) {
        int id = bid - PREP_X_BLOCKS;          // 0..4095
        int wz = id >> 10;                      // 0..3
        int kb = (id >> 5) & 31;
        int nb = id & 31;
        const float* src = (wz == 0) ? wQ : (wz == 1) ? wK : (wz == 2) ? wV : wO;
        size_t dst0 = (size_t)wz * ND * EE;
        int tx = t & 31, ty = t >> 5;
        int k0 = kb * 32, n0 = nb * 32;
        #pragma unroll
        for (int i = 0; i < 4; ++i)
            ts[ty + i*8][tx] = src[(size_t)(k0 + ty + i*8) * ND + n0 + tx];
        __syncthreads();
        #pragma unroll
        for (int i = 0; i < 4; ++i) {
            float v = ts[tx][ty + i*8];
            g_Wh[dst0 + (size_t)(n0 + ty + i*8) * EE + k0 + tx] = __float2half(v);
        }
    } else {
        // mask packing: 2048 blocks x 256 words; warp handles 32 words in
        // groups of 4 with batched loads (MLP=4)
        int pid = bid - PREP_X_BLOCKS - PREP_W_BLOCKS;   // 0..2047
        int wid = t >> 5, lane = t & 31;
        const int wbase = pid * 256 + wid * 32;
        #pragma unroll
        for (int g = 0; g < 8; ++g) {
            int vv[4];
            #pragma unroll
            for (int k = 0; k < 4; ++k) {
                int word = wbase + g*4 + k;
                int col = (word & 63) * 32 + lane;
                int row = word >> 6;
                vv[k] = mask[(size_t)row * SS + col];
            }
            #pragma unroll
            for (int k = 0; k < 4; ++k) {
                uint32_t bits = __ballot_sync(0xffffffffu, vv[k] != 0);
                if (lane == 0) g_mbits[wbase + g*4 + k] = bits;
            }
        }
    }
}

// ---------------------------------------------------------------------------
// fp16 single-pass GEMM: CTA 128x128, BK=64, 8 warps, 3-stage cp.async.
// headmajor=1: z=0 -> Qh (scaled 0.125*log2e), z=1 -> Kh, z=2 -> Vth.
// headmajor=0: fp32 row-major outr.
// ---------------------------------------------------------------------------
#define GBK 64
#define GROWB 144
#define GA_B (128*GROWB)          // 18432
#define GSTAGE (2*GA_B)           // 36864
#define GSMEM_TOTAL (3*GSTAGE)    // 110592

__global__ __launch_bounds__(256) void mma_gemm_kernel(
    int woff, const float* __restrict__ b0, const float* __restrict__ b1,
    const float* __restrict__ b2, int headmajor, float* __restrict__ outr)
{
    extern __shared__ char smc[];
    const uint32_t SB = smem_u32(smc);
    const int t = threadIdx.x;
    const int wid = t >> 5, lane = t & 31;
    const int z = blockIdx.z;
    const int n0 = blockIdx.x * 128;
    const int m0 = blockIdx.y * 128;

    const __half* Wh = g_Wh + (size_t)(woff + z) * ND * EE;
    const float* bias = (z == 0) ? b0 : (z == 1) ? b1 : b2;

    const int wm = (wid & 3) * 32;
    const int wn = (wid >> 2) * 64;

    const int j = lane >> 3, r = lane & 7;
    const int rowA = wm + ((j & 1) << 3) + r;
    const int colA = (j >> 1) << 3;
    const int rowB = wn + ((j >> 1) << 3) + r;
    const int colB = (j & 1) << 3;

    float acc[2][8][4];
    #pragma unroll
    for (int mt = 0; mt < 2; ++mt)
        #pragma unroll
        for (int nt = 0; nt < 8; ++nt)
            #pragma unroll
            for (int q = 0; q < 4; ++q) acc[mt][nt][q] = 0.0f;

    auto load_stage = [&](int kt, int buf) {
        const int k0 = kt * GBK;
        const uint32_t bb = SB + buf * GSTAGE;
        #pragma unroll
        for (int i = 0; i < 4; ++i) {
            int idx = t + i * 256;
            int row = idx >> 3, q = idx & 7;
            cp16(bb + row*GROWB + q*16,        g_Ah + (size_t)(m0 + row) * EE + k0 + q*8);
            cp16(bb + GA_B + row*GROWB + q*16, Wh   + (size_t)(n0 + row) * EE + k0 + q*8);
        }
        cp_commit();
    };

    load_stage(0, 0);
    load_stage(1, 1);
    load_stage(2, 2);

    const int NSTAGE = EE / GBK;   // 16
    int buf = 0;
    for (int kt = 0; kt < NSTAGE; ++kt) {
        if (kt == NSTAGE - 1)      cp_wait<0>();
        else if (kt == NSTAGE - 2) cp_wait<1>();
        else                       cp_wait<2>();
        __syncthreads();
        const uint32_t bb = SB + buf * GSTAGE;

        #pragma unroll
        for (int ks = 0; ks < 4; ++ks) {
            uint32_t ah[2][4];
            #pragma unroll
            for (int mt = 0; mt < 2; ++mt) {
                uint32_t ad = bb + (uint32_t)(rowA + mt*16) * GROWB
                            + (uint32_t)(colA + ks*16) * 2;
                ldsm4(ah[mt], ad);
            }
            #pragma unroll
            for (int ntp = 0; ntp < 4; ++ntp) {
                uint32_t bh[4];
                uint32_t bd = bb + GA_B + (uint32_t)(rowB + ntp*16) * GROWB
                            + (uint32_t)(colB + ks*16) * 2;
                ldsm4(bh, bd);
                #pragma unroll
                for (int sub = 0; sub < 2; ++sub) {
                    uint32_t bb2[2] = {bh[sub*2], bh[sub*2+1]};
                    const int nt = ntp*2 + sub;
                    #pragma unroll
                    for (int mt = 0; mt < 2; ++mt)
                        mma16816(acc[mt][nt], ah[mt], bb2);
                }
            }
        }
        __syncthreads();
        if (kt + 3 < NSTAGE) load_stage(kt + 3, buf);
        buf = (buf == 2) ? 0 : buf + 1;
    }

    const int ncl = (lane & 3) << 1;
    const int mrw = lane >> 2;
    if (headmajor) {
        const int h = (n0 + wn) >> 6;
        if (z < 2) {
            const float sc = (z == 0) ? 0.125f * 1.4426950408889634f : 1.0f;
            __half* dh = z ? g_Kh : g_Qh;
            #pragma unroll
            for (int mt = 0; mt < 2; ++mt) {
                #pragma unroll
                for (int half_ = 0; half_ < 2; ++half_) {
                    int m = m0 + wm + mt*16 + mrw + half_*8;
                    int b_ = m >> 11, s_ = m & (SS - 1);
                    size_t rb = ((size_t)(b_*HH + h) * SS + s_) * DD;
                    #pragma unroll
                    for (int nt = 0; nt < 8; ++nt) {
                        int nn = nt*8 + ncl;
                        float2 bv = *(const float2*)(bias + n0 + wn + nn);
                        float vx = (acc[mt][nt][half_*2+0] + bv.x) * sc;
                        float vy = (acc[mt][nt][half_*2+1] + bv.y) * sc;
                        *(uint32_t*)(dh + rb + nn) = packh(vx, vy);
                    }
                }
            }
        } else {
            #pragma unroll
            for (int mt = 0; mt < 2; ++mt) {
                #pragma unroll
                for (int half_ = 0; half_ < 2; ++half_) {
                    int m = m0 + wm + mt*16 + mrw + half_*8;
                    int b_ = m >> 11, s_ = m & (SS - 1);
                    size_t base = (size_t)(b_*HH + h) * DD * SS;
                    #pragma unroll
                    for (int nt = 0; nt < 8; ++nt) {
                        int nn = nt*8 + ncl;
                        float2 bv = *(const float2*)(bias + n0 + wn + nn);
                        float vx = acc[mt][nt][half_*2+0] + bv.x;
                        float vy = acc[mt][nt][half_*2+1] + bv.y;
                        g_Vth[base + (size_t)nn     * SS + s_] = __float2half(vx);
                        g_Vth[base + (size_t)(nn+1) * SS + s_] = __float2half(vy);
                    }
                }
            }
        }
    } else {
        #pragma unroll
        for (int mt = 0; mt < 2; ++mt) {
            #pragma unroll
            for (int half_ = 0; half_ < 2; ++half_) {
                int m = m0 + wm + mt*16 + mrw + half_*8;
                float* op = outr + (size_t)m * ND + n0 + wn;
                #pragma unroll
                for (int nt = 0; nt < 8; ++nt) {
                    int nn = nt*8 + ncl;
                    float2 bv = *(const float2*)(bias + n0 + wn + nn);
                    float2 v;
                    v.x = acc[mt][nt][half_*2+0] + bv.x;
                    v.y = acc[mt][nt][half_*2+1] + bv.y;
                    *(float2*)(op + nn) = v;
                }
            }
        }
    }
}

// ---------------------------------------------------------------------------
// fp16 MMA flash attention, static-max softmax (unchanged from R12).
// ---------------------------------------------------------------------------
#define AROWB 144
#define AQ_B (128*AROWB)        // 18432
#define AK_B (64*AROWB)         // 9216
#define AOFF_KV 18432
#define AKV_STRIDE 18432
#define ATTN_SMEM (AOFF_KV + 3*AKV_STRIDE)   // 73728

__global__ __launch_bounds__(256, 2) void attn_mma_kernel()
{
    extern __shared__ char smc[];
    const uint32_t SB = smem_u32(smc);
    const int t = threadIdx.x, wid = t >> 5, lane = t & 31;
    const int bh = blockIdx.y, b_ = bh >> 4, h = bh & 15;
    const int q0 = blockIdx.x * 128;
    const int wm = wid * 16;

    const __half* Qh = g_Qh + (size_t)bh*SS*DD + (size_t)q0*DD;
    const __half* Kh = g_Kh + (size_t)bh*SS*DD;
    const __half* Vh = g_Vth + (size_t)bh*DD*SS;

    #pragma unroll
    for (int i = 0; i < 4; ++i) {
        int idx = t + i * 256;
        int row = idx >> 3, q = idx & 7;
        cp16(SB + row*AROWB + q*16, Qh + (size_t)row*DD + q*8);
    }
    auto load_kv = [&](int kt, int buf) {
        const int k0 = kt * 64;
        const uint32_t bb = SB + AOFF_KV + buf * AKV_STRIDE;
        #pragma unroll
        for (int i = 0; i < 2; ++i) {
            int idx = t + i * 256;
            int row = idx >> 3, q = idx & 7;
            cp16(bb + row*AROWB + q*16,        Kh + (size_t)(k0+row)*DD + q*8);
            cp16(bb + AK_B + row*AROWB + q*16, Vh + (size_t)row*SS + k0 + q*8);
        }
        cp_commit();
    };
    load_kv(0, 0);
    load_kv(1, 1);
    load_kv(2, 2);

    const int j = lane >> 3, r_ = lane & 7;
    const int rowA = wm + ((j & 1) << 3) + r_;
    const int colA = (j >> 1) << 3;
    const int rowB = ((j >> 1) << 3) + r_;
    const int colB = (j & 1) << 3;
    const int ncl2 = (lane & 3) << 1;
    const int mrw = lane >> 2;

    const uint32_t* mbp[2];
    #pragma unroll
    for (int hf = 0; hf < 2; ++hf)
        mbp[hf] = g_mbits + (size_t)(b_*SS + q0 + wm + hf*8 + mrw) * (SS/32);

    // hoist Q fragments
    uint32_t aq[4][4];
    cp_wait<2>();
    __syncthreads();
    #pragma unroll
    for (int ks = 0; ks < 4; ++ks)
        ldsm4(aq[ks], SB + (uint32_t)rowA*AROWB + (uint32_t)(colA + ks*16)*2);

    float o[8][4];
    float l_i[2] = {0.0f, 0.0f};
    #pragma unroll
    for (int dn = 0; dn < 8; ++dn)
        #pragma unroll
        for (int q = 0; q < 4; ++q) o[dn][q] = 0.0f;

    const int NKT = SS/64;
    int buf = 0;
    for (int kt = 0; kt < NKT; ++kt) {
        if (kt == NKT - 1)      cp_wait<0>();
        else if (kt == NKT - 2) cp_wait<1>();
        else                    cp_wait<2>();
        __syncthreads();
        const uint32_t bb = SB + AOFF_KV + buf * AKV_STRIDE;

        // prefetch mask words
        uint32_t mw[2][2];
        mw[0][0] = mbp[0][kt*2]; mw[0][1] = mbp[0][kt*2+1];
        mw[1][0] = mbp[1][kt*2]; mw[1][1] = mbp[1][kt*2+1];

        // S = Q K^T
        float s[8][4];
        #pragma unroll
        for (int jn = 0; jn < 8; ++jn)
            #pragma unroll
            for (int q = 0; q < 4; ++q) s[jn][q] = 0.0f;

        #pragma unroll
        for (int ks = 0; ks < 4; ++ks) {
            #pragma unroll
            for (int jnp = 0; jnp < 4; ++jnp) {
                uint32_t kh4[4];
                ldsm4(kh4, bb + (uint32_t)(rowB + jnp*16)*AROWB + (uint32_t)(colB + ks*16)*2);
                #pragma unroll
                for (int sub = 0; sub < 2; ++sub) {
                    uint32_t b2[2] = {kh4[sub*2], kh4[sub*2+1]};
                    mma16816(s[jnp*2 + sub], aq[ks], b2);
                }
            }
        }

        // mask -> -inf, p = exp2(s) in fp16 pairs
        uint32_t pfrag[8][2];
        #pragma unroll
        for (int jn = 0; jn < 8; ++jn) {
            const int sh = (jn*8 + ncl2) & 31;
            uint32_t w0 = mw[0][jn >> 2] >> sh;
            uint32_t w1 = mw[1][jn >> 2] >> sh;
            float s0 = (w0 & 1u) ? s[jn][0] : -1e30f;
            float s1 = (w0 & 2u) ? s[jn][1] : -1e30f;
            float s2 = (w1 & 1u) ? s[jn][2] : -1e30f;
            float s3 = (w1 & 2u) ? s[jn][3] : -1e30f;
            pfrag[jn][0] = h2ex2(packh(s0, s1));
            pfrag[jn][1] = h2ex2(packh(s2, s3));
        }

        // row-sum on fma pipe (fp32)
        #pragma unroll
        for (int hf = 0; hf < 2; ++hf) {
            float acc = 0.0f;
            #pragma unroll
            for (int jn = 0; jn < 8; ++jn) {
                float2 f = __half22float2(*reinterpret_cast<__half2*>(&pfrag[jn][hf]));
                acc += f.x + f.y;
            }
            acc += __shfl_xor_sync(0xffffffffu, acc, 1);
            acc += __shfl_xor_sync(0xffffffffu, acc, 2);
            l_i[hf] += acc;
        }

        // O += P V
        #pragma unroll
        for (int ks = 0; ks < 4; ++ks) {
            uint32_t pah[4] = {pfrag[2*ks][0], pfrag[2*ks][1],
                               pfrag[2*ks+1][0], pfrag[2*ks+1][1]};
            #pragma unroll
            for (int dnp = 0; dnp < 4; ++dnp) {
                uint32_t vh4[4];
                ldsm4(vh4, bb + AK_B + (uint32_t)(rowB + dnp*16)*AROWB
                           + (uint32_t)(colB + ks*16)*2);
                #pragma unroll
                for (int sub = 0; sub < 2; ++sub) {
                    uint32_t v2[2] = {vh4[sub*2], vh4[sub*2+1]};
                    mma16816(o[dnp*2 + sub], pah, v2);
                }
            }
        }

        __syncthreads();
        if (kt + 3 < NKT) load_kv(kt + 3, buf);
        buf = (buf == 2) ? 0 : buf + 1;
    }

    // normalize + write fp16 to out-proj A buffer [m][h*64+d]
    #pragma unroll
    for (int hf = 0; hf < 2; ++hf) {
        const int q = q0 + wm + hf*8 + mrw;
        const float inv = 1.0f / l_i[hf];
        size_t base = ((size_t)b_*SS + q) * ND + h*64;
        #pragma unroll
        for (int dn = 0; dn < 8; ++dn) {
            int d0 = dn*8 + ncl2;
            *(uint32_t*)(g_Ah + base + d0) =
                packh(o[dn][hf*2] * inv, o[dn][hf*2+1] * inv);
        }
    }
}

extern "C" void kernel_launch(void* const* d_in, const int* in_sizes, int n_in,
                              void* d_out, int out_size)
{
    const float* X    = (const float*)d_in[0];
    const int*   mask = (const int*)  d_in[1];
    const float* wQ   = (const float*)d_in[2];
    const float* bQ   = (const float*)d_in[3];
    const float* wK   = (const float*)d_in[4];
    const float* bK   = (const float*)d_in[5];
    const float* wV   = (const float*)d_in[6];
    const float* bV   = (const float*)d_in[7];
    const float* wO   = (const float*)d_in[8];
    const float* bO   = (const float*)d_in[9];
    float* out = (float*)d_out;

    cudaFuncSetAttribute(mma_gemm_kernel, cudaFuncAttributeMaxDynamicSharedMemorySize, GSMEM_TOTAL);
    cudaFuncSetAttribute(attn_mma_kernel, cudaFuncAttributeMaxDynamicSharedMemorySize, ATTN_SMEM);

    prep_kernel<<<PREP_BLOCKS, 256>>>(X, mask, wQ, wK, wV, wO);
    mma_gemm_kernel<<<dim3(8, 64, 3), 256, GSMEM_TOTAL>>>(0, bQ, bK, bV, 1, nullptr);
    attn_mma_kernel<<<dim3(16, 64), 256, ATTN_SMEM>>>();
    mma_gemm_kernel<<<dim3(8, 64, 1), 256, GSMEM_TOTAL>>>(3, bO, bO, bO, 0, out);
}

// round 14
// speedup vs baseline: 1.5534x; 1.0004x over previous
#include <cuda_runtime.h>
#include <cuda_fp16.h>
#include <math.h>
#include <stdint.h>

#define BB 4
#define SS 2048
#define EE 1024
#define HH 16
#define DD 64
#define ND 1024
#define MM (BB*SS)   // 8192

// fp16 operands
__device__ __half g_Ah[MM*EE];          // GEMM A (X, later attention output)
__device__ __half g_Wh[4*ND*EE];        // weights transposed [z][n][k]
__device__ __half g_Qh[BB*HH*SS*DD];    // Q head-major (pre-scaled by 0.125*log2e)
__device__ __half g_Kh[BB*HH*SS*DD];    // K head-major
__device__ __half g_Vth[BB*HH*DD*SS];   // V transposed [bh][d][s]
// packed mask bits
__device__ uint32_t g_mbits[BB*SS*(SS/32)];

// ---------------------------------------------------------------------------
// PTX helpers (compute_103-safe)
// ---------------------------------------------------------------------------
__device__ __forceinline__ uint32_t smem_u32(const void* p) {
    return (uint32_t)__cvta_generic_to_shared(p);
}
__device__ __forceinline__ void ldsm4(uint32_t* r, uint32_t addr) {
    asm volatile("ldmatrix.sync.aligned.m8n8.x4.shared.b16 {%0,%1,%2,%3}, [%4];"
                 : "=r"(r[0]), "=r"(r[1]), "=r"(r[2]), "=r"(r[3]) : "r"(addr));
}
__device__ __forceinline__ void mma16816(float* c, const uint32_t* a, const uint32_t* b) {
    asm volatile("mma.sync.aligned.m16n8k16.row.col.f32.f16.f16.f32 "
                 "{%0,%1,%2,%3}, {%4,%5,%6,%7}, {%8,%9}, {%0,%1,%2,%3};"
                 : "+f"(c[0]), "+f"(c[1]), "+f"(c[2]), "+f"(c[3])
                 : "r"(a[0]), "r"(a[1]), "r"(a[2]), "r"(a[3]), "r"(b[0]), "r"(b[1]));
}
__device__ __forceinline__ void cp16(uint32_t dst, const void* src) {
    asm volatile("cp.async.cg.shared.global [%0], [%1], 16;" :: "r"(dst), "l"(src) : "memory");
}
__device__ __forceinline__ void cp_commit() {
    asm volatile("cp.async.commit_group;" ::: "memory");
}
template <int N>
__device__ __forceinline__ void cp_wait() {
    asm volatile("cp.async.wait_group %0;" :: "n"(N) : "memory");
}
__device__ __forceinline__ uint32_t packh(float a, float b) {
    __half2 t = __floats2half2_rn(a, b);
    return *reinterpret_cast<uint32_t*>(&t);
}
__device__ __forceinline__ uint32_t h2ex2(uint32_t x) {
    uint32_t y;
    asm volatile("ex2.approx.f16x2 %0, %1;" : "=r"(y) : "r"(x));
    return y;
}

// ---------------------------------------------------------------------------
// Prep kernel (X + W only; mask pack is a separate overlapped kernel):
//   blocks [0, 2048)      : X fp32 -> g_Ah fp16, 4 float4 loads per thread
//   blocks [2048, 6144)   : weights fp32 -> g_Wh fp16 transposed (smem)
// ---------------------------------------------------------------------------
#define PREP_X_BLOCKS 2048
#define PREP_W_BLOCKS 4096
#define PREP_BLOCKS (PREP_X_BLOCKS + PREP_W_BLOCKS)

__global__ __launch_bounds__(256) void prep_kernel(
    const float* __restrict__ X,
    const float* __restrict__ wQ, const float* __restrict__ wK,
    const float* __restrict__ wV, const float* __restrict__ wO)
{
    __shared__ float ts[32][33];
    const int bid = blockIdx.x;
    const int t = threadIdx.x;

    if (bid < PREP_X_BLOCKS) {
        float4 v[4];
        int i4b = bid * 1024 + t;
        #pragma unroll
        for (int i = 0; i < 4; ++i)
            v[i] = *(const float4*)(X + (size_t)(i4b + i*256) * 4);
        #pragma unroll
        for (int i = 0; i < 4; ++i) {
            size_t o = (size_t)(i4b + i*256) * 4;
            *(uint32_t*)(g_Ah + o)     = packh(v[i].x, v[i].y);
            *(uint32_t*)(g_Ah + o + 2) = packh(v[i].z, v[i].w);
        }
    } else {
        int id = bid - PREP_X_BLOCKS;          // 0..4095
        int wz = id >> 10;
        int kb = (id >> 5) & 31;
        int nb = id & 31;
        const float* src = (wz == 0) ? wQ : (wz == 1) ? wK : (wz == 2) ? wV : wO;
        size_t dst0 = (size_t)wz * ND * EE;
        int tx = t & 31, ty = t >> 5;
        int k0 = kb * 32, n0 = nb * 32;
        #pragma unroll
        for (int i = 0; i < 4; ++i)
            ts[ty + i*8][tx] = src[(size_t)(k0 + ty + i*8) * ND + n0 + tx];
        __syncthreads();
        #pragma unroll
        for (int i = 0; i < 4; ++i) {
            float v = ts[tx][ty + i*8];
            g_Wh[dst0 + (size_t)(n0 + ty + i*8) * EE + k0 + tx] = __float2half(v);
        }
    }
}

// standalone mask pack (overlapped with qkv GEMM on a forked stream)
__global__ __launch_bounds__(256) void pack_mask_kernel(const int* __restrict__ mask)
{
    int pid = blockIdx.x;                       // 0..2047
    int wid = threadIdx.x >> 5, lane = threadIdx.x & 31;
    const int wbase = pid * 256 + wid * 32;
    #pragma unroll
    for (int g = 0; g < 8; ++g) {
        int vv[4];
        #pragma unroll
        for (int k = 0; k < 4; ++k) {
            int word = wbase + g*4 + k;
            int col = (word & 63) * 32 + lane;
            int row = word >> 6;
            vv[k] = mask[(size_t)row * SS + col];
        }
        #pragma unroll
        for (int k = 0; k < 4; ++k) {
            uint32_t bits = __ballot_sync(0xffffffffu, vv[k] != 0);
            if (lane == 0) g_mbits[wbase + g*4 + k] = bits;
        }
    }
}

// ---------------------------------------------------------------------------
// fp16 single-pass GEMM (unchanged from R13).
// ---------------------------------------------------------------------------
#define GBK 64
#define GROWB 144
#define GA_B (128*GROWB)          // 18432
#define GSTAGE (2*GA_B)           // 36864
#define GSMEM_TOTAL (3*GSTAGE)    // 110592

__global__ __launch_bounds__(256) void mma_gemm_kernel(
    int woff, const float* __restrict__ b0, const float* __restrict__ b1,
    const float* __restrict__ b2, int headmajor, float* __restrict__ outr)
{
    extern __shared__ char smc[];
    const uint32_t SB = smem_u32(smc);
    const int t = threadIdx.x;
    const int wid = t >> 5, lane = t & 31;
    const int z = blockIdx.z;
    const int n0 = blockIdx.x * 128;
    const int m0 = blockIdx.y * 128;

    const __half* Wh = g_Wh + (size_t)(woff + z) * ND * EE;
    const float* bias = (z == 0) ? b0 : (z == 1) ? b1 : b2;

    const int wm = (wid & 3) * 32;
    const int wn = (wid >> 2) * 64;

    const int j = lane >> 3, r = lane & 7;
    const int rowA = wm + ((j & 1) << 3) + r;
    const int colA = (j >> 1) << 3;
    const int rowB = wn + ((j >> 1) << 3) + r;
    const int colB = (j & 1) << 3;

    float acc[2][8][4];
    #pragma unroll
    for (int mt = 0; mt < 2; ++mt)
        #pragma unroll
        for (int nt = 0; nt < 8; ++nt)
            #pragma unroll
            for (int q = 0; q < 4; ++q) acc[mt][nt][q] = 0.0f;

    auto load_stage = [&](int kt, int buf) {
        const int k0 = kt * GBK;
        const uint32_t bb = SB + buf * GSTAGE;
        #pragma unroll
        for (int i = 0; i < 4; ++i) {
            int idx = t + i * 256;
            int row = idx >> 3, q = idx & 7;
            cp16(bb + row*GROWB + q*16,        g_Ah + (size_t)(m0 + row) * EE + k0 + q*8);
            cp16(bb + GA_B + row*GROWB + q*16, Wh   + (size_t)(n0 + row) * EE + k0 + q*8);
        }
        cp_commit();
    };

    load_stage(0, 0);
    load_stage(1, 1);
    load_stage(2, 2);

    const int NSTAGE = EE / GBK;   // 16
    int buf = 0;
    for (int kt = 0; kt < NSTAGE; ++kt) {
        if (kt == NSTAGE - 1)      cp_wait<0>();
        else if (kt == NSTAGE - 2) cp_wait<1>();
        else                       cp_wait<2>();
        __syncthreads();
        const uint32_t bb = SB + buf * GSTAGE;

        #pragma unroll
        for (int ks = 0; ks < 4; ++ks) {
            uint32_t ah[2][4];
            #pragma unroll
            for (int mt = 0; mt < 2; ++mt) {
                uint32_t ad = bb + (uint32_t)(rowA + mt*16) * GROWB
                            + (uint32_t)(colA + ks*16) * 2;
                ldsm4(ah[mt], ad);
            }
            #pragma unroll
            for (int ntp = 0; ntp < 4; ++ntp) {
                uint32_t bh[4];
                uint32_t bd = bb + GA_B + (uint32_t)(rowB + ntp*16) * GROWB
                            + (uint32_t)(colB + ks*16) * 2;
                ldsm4(bh, bd);
                #pragma unroll
                for (int sub = 0; sub < 2; ++sub) {
                    uint32_t bb2[2] = {bh[sub*2], bh[sub*2+1]};
                    const int nt = ntp*2 + sub;
                    #pragma unroll
                    for (int mt = 0; mt < 2; ++mt)
                        mma16816(acc[mt][nt], ah[mt], bb2);
                }
            }
        }
        __syncthreads();
        if (kt + 3 < NSTAGE) load_stage(kt + 3, buf);
        buf = (buf == 2) ? 0 : buf + 1;
    }

    const int ncl = (lane & 3) << 1;
    const int mrw = lane >> 2;
    if (headmajor) {
        const int h = (n0 + wn) >> 6;
        if (z < 2) {
            const float sc = (z == 0) ? 0.125f * 1.4426950408889634f : 1.0f;
            __half* dh = z ? g_Kh : g_Qh;
            #pragma unroll
            for (int mt = 0; mt < 2; ++mt) {
                #pragma unroll
                for (int half_ = 0; half_ < 2; ++half_) {
                    int m = m0 + wm + mt*16 + mrw + half_*8;
                    int b_ = m >> 11, s_ = m & (SS - 1);
                    size_t rb = ((size_t)(b_*HH + h) * SS + s_) * DD;
                    #pragma unroll
                    for (int nt = 0; nt < 8; ++nt) {
                        int nn = nt*8 + ncl;
                        float2 bv = *(const float2*)(bias + n0 + wn + nn);
                        float vx = (acc[mt][nt][half_*2+0] + bv.x) * sc;
                        float vy = (acc[mt][nt][half_*2+1] + bv.y) * sc;
                        *(uint32_t*)(dh + rb + nn) = packh(vx, vy);
                    }
                }
            }
        } else {
            #pragma unroll
            for (int mt = 0; mt < 2; ++mt) {
                #pragma unroll
                for (int half_ = 0; half_ < 2; ++half_) {
                    int m = m0 + wm + mt*16 + mrw + half_*8;
                    int b_ = m >> 11, s_ = m & (SS - 1);
                    size_t base = (size_t)(b_*HH + h) * DD * SS;
                    #pragma unroll
                    for (int nt = 0; nt < 8; ++nt) {
                        int nn = nt*8 + ncl;
                        float2 bv = *(const float2*)(bias + n0 + wn + nn);
                        float vx = acc[mt][nt][half_*2+0] + bv.x;
                        float vy = acc[mt][nt][half_*2+1] + bv.y;
                        g_Vth[base + (size_t)nn     * SS + s_] = __float2half(vx);
                        g_Vth[base + (size_t)(nn+1) * SS + s_] = __float2half(vy);
                    }
                }
            }
        }
    } else {
        #pragma unroll
        for (int mt = 0; mt < 2; ++mt) {
            #pragma unroll
            for (int half_ = 0; half_ < 2; ++half_) {
                int m = m0 + wm + mt*16 + mrw + half_*8;
                float* op = outr + (size_t)m * ND + n0 + wn;
                #pragma unroll
                for (int nt = 0; nt < 8; ++nt) {
                    int nn = nt*8 + ncl;
                    float2 bv = *(const float2*)(bias + n0 + wn + nn);
                    float2 v;
                    v.x = acc[mt][nt][half_*2+0] + bv.x;
                    v.y = acc[mt][nt][half_*2+1] + bv.y;
                    *(float2*)(op + nn) = v;
                }
            }
        }
    }
}

// ---------------------------------------------------------------------------
// fp16 MMA flash attention, static-max softmax (unchanged from R13).
// ---------------------------------------------------------------------------
#define AROWB 144
#define AQ_B (128*AROWB)        // 18432
#define AK_B (64*AROWB)         // 9216
#define AOFF_KV 18432
#define AKV_STRIDE 18432
#define ATTN_SMEM (AOFF_KV + 3*AKV_STRIDE)   // 73728

__global__ __launch_bounds__(256, 2) void attn_mma_kernel()
{
    extern __shared__ char smc[];
    const uint32_t SB = smem_u32(smc);
    const int t = threadIdx.x, wid = t >> 5, lane = t & 31;
    const int bh = blockIdx.y, b_ = bh >> 4, h = bh & 15;
    const int q0 = blockIdx.x * 128;
    const int wm = wid * 16;

    const __half* Qh = g_Qh + (size_t)bh*SS*DD + (size_t)q0*DD;
    const __half* Kh = g_Kh + (size_t)bh*SS*DD;
    const __half* Vh = g_Vth + (size_t)bh*DD*SS;

    #pragma unroll
    for (int i = 0; i < 4; ++i) {
        int idx = t + i * 256;
        int row = idx >> 3, q = idx & 7;
        cp16(SB + row*AROWB + q*16, Qh + (size_t)row*DD + q*8);
    }
    auto load_kv = [&](int kt, int buf) {
        const int k0 = kt * 64;
        const uint32_t bb = SB + AOFF_KV + buf * AKV_STRIDE;
        #pragma unroll
        for (int i = 0; i < 2; ++i) {
            int idx = t + i * 256;
            int row = idx >> 3, q = idx & 7;
            cp16(bb + row*AROWB + q*16,        Kh + (size_t)(k0+row)*DD + q*8);
            cp16(bb + AK_B + row*AROWB + q*16, Vh + (size_t)row*SS + k0 + q*8);
        }
        cp_commit();
    };
    load_kv(0, 0);
    load_kv(1, 1);
    load_kv(2, 2);

    const int j = lane >> 3, r_ = lane & 7;
    const int rowA = wm + ((j & 1) << 3) + r_;
    const int colA = (j >> 1) << 3;
    const int rowB = ((j >> 1) << 3) + r_;
    const int colB = (j & 1) << 3;
    const int ncl2 = (lane & 3) << 1;
    const int mrw = lane >> 2;

    const uint32_t* mbp[2];
    #pragma unroll
    for (int hf = 0; hf < 2; ++hf)
        mbp[hf] = g_mbits + (size_t)(b_*SS + q0 + wm + hf*8 + mrw) * (SS/32);

    uint32_t aq[4][4];
    cp_wait<2>();
    __syncthreads();
    #pragma unroll
    for (int ks = 0; ks < 4; ++ks)
        ldsm4(aq[ks], SB + (uint32_t)rowA*AROWB + (uint32_t)(colA + ks*16)*2);

    float o[8][4];
    float l_i[2] = {0.0f, 0.0f};
    #pragma unroll
    for (int dn = 0; dn < 8; ++dn)
        #pragma unroll
        for (int q = 0; q < 4; ++q) o[dn][q] = 0.0f;

    const int NKT = SS/64;
    int buf = 0;
    for (int kt = 0; kt < NKT; ++kt) {
        if (kt == NKT - 1)      cp_wait<0>();
        else if (kt == NKT - 2) cp_wait<1>();
        else                    cp_wait<2>();
        __syncthreads();
        const uint32_t bb = SB + AOFF_KV + buf * AKV_STRIDE;

        uint32_t mw[2][2];
        mw[0][0] = mbp[0][kt*2]; mw[0][1] = mbp[0][kt*2+1];
        mw[1][0] = mbp[1][kt*2]; mw[1][1] = mbp[1][kt*2+1];

        float s[8][4];
        #pragma unroll
        for (int jn = 0; jn < 8; ++jn)
            #pragma unroll
            for (int q = 0; q < 4; ++q) s[jn][q] = 0.0f;

        #pragma unroll
        for (int ks = 0; ks < 4; ++ks) {
            #pragma unroll
            for (int jnp = 0; jnp < 4; ++jnp) {
                uint32_t kh4[4];
                ldsm4(kh4, bb + (uint32_t)(rowB + jnp*16)*AROWB + (uint32_t)(colB + ks*16)*2);
                #pragma unroll
                for (int sub = 0; sub < 2; ++sub) {
                    uint32_t b2[2] = {kh4[sub*2], kh4[sub*2+1]};
                    mma16816(s[jnp*2 + sub], aq[ks], b2);
                }
            }
        }

        uint32_t pfrag[8][2];
        #pragma unroll
        for (int jn = 0; jn < 8; ++jn) {
            const int sh = (jn*8 + ncl2) & 31;
            uint32_t w0 = mw[0][jn >> 2] >> sh;
            uint32_t w1 = mw[1][jn >> 2] >> sh;
            float s0 = (w0 & 1u) ? s[jn][0] : -1e30f;
            float s1 = (w0 & 2u) ? s[jn][1] : -1e30f;
            float s2 = (w1 & 1u) ? s[jn][2] : -1e30f;
            float s3 = (w1 & 2u) ? s[jn][3] : -1e30f;
            pfrag[jn][0] = h2ex2(packh(s0, s1));
            pfrag[jn][1] = h2ex2(packh(s2, s3));
        }

        #pragma unroll
        for (int hf = 0; hf < 2; ++hf) {
            float acc = 0.0f;
            #pragma unroll
            for (int jn = 0; jn < 8; ++jn) {
                float2 f = __half22float2(*reinterpret_cast<__half2*>(&pfrag[jn][hf]));
                acc += f.x + f.y;
            }
            acc += __shfl_xor_sync(0xffffffffu, acc, 1);
            acc += __shfl_xor_sync(0xffffffffu, acc, 2);
            l_i[hf] += acc;
        }

        #pragma unroll
        for (int ks = 0; ks < 4; ++ks) {
            uint32_t pah[4] = {pfrag[2*ks][0], pfrag[2*ks][1],
                               pfrag[2*ks+1][0], pfrag[2*ks+1][1]};
            #pragma unroll
            for (int dnp = 0; dnp < 4; ++dnp) {
                uint32_t vh4[4];
                ldsm4(vh4, bb + AK_B + (uint32_t)(rowB + dnp*16)*AROWB
                           + (uint32_t)(colB + ks*16)*2);
                #pragma unroll
                for (int sub = 0; sub < 2; ++sub) {
                    uint32_t v2[2] = {vh4[sub*2], vh4[sub*2+1]};
                    mma16816(o[dnp*2 + sub], pah, v2);
                }
            }
        }

        __syncthreads();
        if (kt + 3 < NKT) load_kv(kt + 3, buf);
        buf = (buf == 2) ? 0 : buf + 1;
    }

    #pragma unroll
    for (int hf = 0; hf < 2; ++hf) {
        const int q = q0 + wm + hf*8 + mrw;
        const float inv = 1.0f / l_i[hf];
        size_t base = ((size_t)b_*SS + q) * ND + h*64;
        #pragma unroll
        for (int dn = 0; dn < 8; ++dn) {
            int d0 = dn*8 + ncl2;
            *(uint32_t*)(g_Ah + base + d0) =
                packh(o[dn][hf*2] * inv, o[dn][hf*2+1] * inv);
        }
    }
}

extern "C" void kernel_launch(void* const* d_in, const int* in_sizes, int n_in,
                              void* d_out, int out_size)
{
    const float* X    = (const float*)d_in[0];
    const int*   mask = (const int*)  d_in[1];
    const float* wQ   = (const float*)d_in[2];
    const float* bQ   = (const float*)d_in[3];
    const float* wK   = (const float*)d_in[4];
    const float* bK   = (const float*)d_in[5];
    const float* wV   = (const float*)d_in[6];
    const float* bV   = (const float*)d_in[7];
    const float* wO   = (const float*)d_in[8];
    const float* bO   = (const float*)d_in[9];
    float* out = (float*)d_out;

    cudaFuncSetAttribute(mma_gemm_kernel, cudaFuncAttributeMaxDynamicSharedMemorySize, GSMEM_TOTAL);
    cudaFuncSetAttribute(attn_mma_kernel, cudaFuncAttributeMaxDynamicSharedMemorySize, ATTN_SMEM);

    // fork a side stream so mask packing overlaps the qkv GEMM in the graph
    cudaStream_t s2;
    cudaStreamCreate(&s2);
    cudaEvent_t evFork, evJoin;
    cudaEventCreateWithFlags(&evFork, cudaEventDisableTiming);
    cudaEventCreateWithFlags(&evJoin, cudaEventDisableTiming);

    prep_kernel<<<PREP_BLOCKS, 256>>>(X, wQ, wK, wV, wO);

    cudaEventRecord(evFork, 0);
    cudaStreamWaitEvent(s2, evFork, 0);
    pack_mask_kernel<<<2048, 256, 0, s2>>>(mask);      // overlaps with qkv below
    cudaEventRecord(evJoin, s2);

    mma_gemm_kernel<<<dim3(8, 64, 3), 256, GSMEM_TOTAL>>>(0, bQ, bK, bV, 1, nullptr);

    cudaStreamWaitEvent(0, evJoin, 0);                 // attention needs the bitmask
    attn_mma_kernel<<<dim3(16, 64), 256, ATTN_SMEM>>>();
    mma_gemm_kernel<<<dim3(8, 64, 1), 256, GSMEM_TOTAL>>>(3, bO, bO, bO, 0, out);

    cudaEventDestroy(evFork);
    cudaEventDestroy(evJoin);
    cudaStreamDestroy(s2);
}

// round 15
// speedup vs baseline: 1.6357x; 1.0530x over previous
#include <cuda_runtime.h>
#include <cuda_fp16.h>
#include <math.h>
#include <stdint.h>

#define BB 4
#define SS 2048
#define EE 1024
#define HH 16
#define DD 64
#define ND 1024
#define MM (BB*SS)   // 8192

// fp16 operands
__device__ __half g_Ah[MM*EE];          // GEMM A (X, later attention output)
__device__ __half g_Wh[4*ND*EE];        // weights transposed [z][n][k]
__device__ __half g_Qh[BB*HH*SS*DD];    // Q head-major (pre-scaled by 0.125*log2e)
__device__ __half g_Kh[BB*HH*SS*DD];    // K head-major
__device__ __half g_Vth[BB*HH*DD*SS];   // V transposed [bh][d][s]
// packed mask bits
__device__ uint32_t g_mbits[BB*SS*(SS/32)];

// ---------------------------------------------------------------------------
// PTX helpers (compute_103-safe)
// ---------------------------------------------------------------------------
__device__ __forceinline__ uint32_t smem_u32(const void* p) {
    return (uint32_t)__cvta_generic_to_shared(p);
}
__device__ __forceinline__ void ldsm4(uint32_t* r, uint32_t addr) {
    asm volatile("ldmatrix.sync.aligned.m8n8.x4.shared.b16 {%0,%1,%2,%3}, [%4];"
                 : "=r"(r[0]), "=r"(r[1]), "=r"(r[2]), "=r"(r[3]) : "r"(addr));
}
__device__ __forceinline__ void mma16816(float* c, const uint32_t* a, const uint32_t* b) {
    asm volatile("mma.sync.aligned.m16n8k16.row.col.f32.f16.f16.f32 "
                 "{%0,%1,%2,%3}, {%4,%5,%6,%7}, {%8,%9}, {%0,%1,%2,%3};"
                 : "+f"(c[0]), "+f"(c[1]), "+f"(c[2]), "+f"(c[3])
                 : "r"(a[0]), "r"(a[1]), "r"(a[2]), "r"(a[3]), "r"(b[0]), "r"(b[1]));
}
__device__ __forceinline__ void cp16(uint32_t dst, const void* src) {
    asm volatile("cp.async.cg.shared.global [%0], [%1], 16;" :: "r"(dst), "l"(src) : "memory");
}
__device__ __forceinline__ void cp_commit() {
    asm volatile("cp.async.commit_group;" ::: "memory");
}
template <int N>
__device__ __forceinline__ void cp_wait() {
    asm volatile("cp.async.wait_group %0;" :: "n"(N) : "memory");
}
__device__ __forceinline__ uint32_t packh(float a, float b) {
    __half2 t = __floats2half2_rn(a, b);
    return *reinterpret_cast<uint32_t*>(&t);
}
__device__ __forceinline__ uint32_t h2ex2(uint32_t x) {
    uint32_t y;
    asm volatile("ex2.approx.f16x2 %0, %1;" : "=r"(y) : "r"(x));
    return y;
}

// ---------------------------------------------------------------------------
// Prep kernel (X + W only; mask pack separate, overlapped):
// ---------------------------------------------------------------------------
#define PREP_X_BLOCKS 2048
#define PREP_W_BLOCKS 4096
#define PREP_BLOCKS (PREP_X_BLOCKS + PREP_W_BLOCKS)

__global__ __launch_bounds__(256) void prep_kernel(
    const float* __restrict__ X,
    const float* __restrict__ wQ, const float* __restrict__ wK,
    const float* __restrict__ wV, const float* __restrict__ wO)
{
    __shared__ float ts[32][33];
    const int bid = blockIdx.x;
    const int t = threadIdx.x;

    if (bid < PREP_X_BLOCKS) {
        float4 v[4];
        int i4b = bid * 1024 + t;
        #pragma unroll
        for (int i = 0; i < 4; ++i)
            v[i] = *(const float4*)(X + (size_t)(i4b + i*256) * 4);
        #pragma unroll
        for (int i = 0; i < 4; ++i) {
            size_t o = (size_t)(i4b + i*256) * 4;
            *(uint32_t*)(g_Ah + o)     = packh(v[i].x, v[i].y);
            *(uint32_t*)(g_Ah + o + 2) = packh(v[i].z, v[i].w);
        }
    } else {
        int id = bid - PREP_X_BLOCKS;
        int wz = id >> 10;
        int kb = (id >> 5) & 31;
        int nb = id & 31;
        const float* src = (wz == 0) ? wQ : (wz == 1) ? wK : (wz == 2) ? wV : wO;
        size_t dst0 = (size_t)wz * ND * EE;
        int tx = t & 31, ty = t >> 5;
        int k0 = kb * 32, n0 = nb * 32;
        #pragma unroll
        for (int i = 0; i < 4; ++i)
            ts[ty + i*8][tx] = src[(size_t)(k0 + ty + i*8) * ND + n0 + tx];
        __syncthreads();
        #pragma unroll
        for (int i = 0; i < 4; ++i) {
            float v = ts[tx][ty + i*8];
            g_Wh[dst0 + (size_t)(n0 + ty + i*8) * EE + k0 + tx] = __float2half(v);
        }
    }
}

// standalone mask pack (overlapped with qkv GEMM on a forked stream)
__global__ __launch_bounds__(256) void pack_mask_kernel(const int* __restrict__ mask)
{
    int pid = blockIdx.x;
    int wid = threadIdx.x >> 5, lane = threadIdx.x & 31;
    const int wbase = pid * 256 + wid * 32;
    #pragma unroll
    for (int g = 0; g < 8; ++g) {
        int vv[4];
        #pragma unroll
        for (int k = 0; k < 4; ++k) {
            int word = wbase + g*4 + k;
            int col = (word & 63) * 32 + lane;
            int row = word >> 6;
            vv[k] = mask[(size_t)row * SS + col];
        }
        #pragma unroll
        for (int k = 0; k < 4; ++k) {
            uint32_t bits = __ballot_sync(0xffffffffu, vv[k] != 0);
            if (lane == 0) g_mbits[wbase + g*4 + k] = bits;
        }
    }
}

// ---------------------------------------------------------------------------
// fp16 single-pass GEMM (unchanged).
// ---------------------------------------------------------------------------
#define GBK 64
#define GROWB 144
#define GA_B (128*GROWB)          // 18432
#define GSTAGE (2*GA_B)           // 36864
#define GSMEM_TOTAL (3*GSTAGE)    // 110592

__global__ __launch_bounds__(256) void mma_gemm_kernel(
    int woff, const float* __restrict__ b0, const float* __restrict__ b1,
    const float* __restrict__ b2, int headmajor, float* __restrict__ outr)
{
    extern __shared__ char smc[];
    const uint32_t SB = smem_u32(smc);
    const int t = threadIdx.x;
    const int wid = t >> 5, lane = t & 31;
    const int z = blockIdx.z;
    const int n0 = blockIdx.x * 128;
    const int m0 = blockIdx.y * 128;

    const __half* Wh = g_Wh + (size_t)(woff + z) * ND * EE;
    const float* bias = (z == 0) ? b0 : (z == 1) ? b1 : b2;

    const int wm = (wid & 3) * 32;
    const int wn = (wid >> 2) * 64;

    const int j = lane >> 3, r = lane & 7;
    const int rowA = wm + ((j & 1) << 3) + r;
    const int colA = (j >> 1) << 3;
    const int rowB = wn + ((j >> 1) << 3) + r;
    const int colB = (j & 1) << 3;

    float acc[2][8][4];
    #pragma unroll
    for (int mt = 0; mt < 2; ++mt)
        #pragma unroll
        for (int nt = 0; nt < 8; ++nt)
            #pragma unroll
            for (int q = 0; q < 4; ++q) acc[mt][nt][q] = 0.0f;

    auto load_stage = [&](int kt, int buf) {
        const int k0 = kt * GBK;
        const uint32_t bb = SB + buf * GSTAGE;
        #pragma unroll
        for (int i = 0; i < 4; ++i) {
            int idx = t + i * 256;
            int row = idx >> 3, q = idx & 7;
            cp16(bb + row*GROWB + q*16,        g_Ah + (size_t)(m0 + row) * EE + k0 + q*8);
            cp16(bb + GA_B + row*GROWB + q*16, Wh   + (size_t)(n0 + row) * EE + k0 + q*8);
        }
        cp_commit();
    };

    load_stage(0, 0);
    load_stage(1, 1);
    load_stage(2, 2);

    const int NSTAGE = EE / GBK;   // 16
    int buf = 0;
    for (int kt = 0; kt < NSTAGE; ++kt) {
        if (kt == NSTAGE - 1)      cp_wait<0>();
        else if (kt == NSTAGE - 2) cp_wait<1>();
        else                       cp_wait<2>();
        __syncthreads();
        const uint32_t bb = SB + buf * GSTAGE;

        #pragma unroll
        for (int ks = 0; ks < 4; ++ks) {
            uint32_t ah[2][4];
            #pragma unroll
            for (int mt = 0; mt < 2; ++mt) {
                uint32_t ad = bb + (uint32_t)(rowA + mt*16) * GROWB
                            + (uint32_t)(colA + ks*16) * 2;
                ldsm4(ah[mt], ad);
            }
            #pragma unroll
            for (int ntp = 0; ntp < 4; ++ntp) {
                uint32_t bh[4];
                uint32_t bd = bb + GA_B + (uint32_t)(rowB + ntp*16) * GROWB
                            + (uint32_t)(colB + ks*16) * 2;
                ldsm4(bh, bd);
                #pragma unroll
                for (int sub = 0; sub < 2; ++sub) {
                    uint32_t bb2[2] = {bh[sub*2], bh[sub*2+1]};
                    const int nt = ntp*2 + sub;
                    #pragma unroll
                    for (int mt = 0; mt < 2; ++mt)
                        mma16816(acc[mt][nt], ah[mt], bb2);
                }
            }
        }
        __syncthreads();
        if (kt + 3 < NSTAGE) load_stage(kt + 3, buf);
        buf = (buf == 2) ? 0 : buf + 1;
    }

    const int ncl = (lane & 3) << 1;
    const int mrw = lane >> 2;
    if (headmajor) {
        const int h = (n0 + wn) >> 6;
        if (z < 2) {
            const float sc = (z == 0) ? 0.125f * 1.4426950408889634f : 1.0f;
            __half* dh = z ? g_Kh : g_Qh;
            #pragma unroll
            for (int mt = 0; mt < 2; ++mt) {
                #pragma unroll
                for (int half_ = 0; half_ < 2; ++half_) {
                    int m = m0 + wm + mt*16 + mrw + half_*8;
                    int b_ = m >> 11, s_ = m & (SS - 1);
                    size_t rb = ((size_t)(b_*HH + h) * SS + s_) * DD;
                    #pragma unroll
                    for (int nt = 0; nt < 8; ++nt) {
                        int nn = nt*8 + ncl;
                        float2 bv = *(const float2*)(bias + n0 + wn + nn);
                        float vx = (acc[mt][nt][half_*2+0] + bv.x) * sc;
                        float vy = (acc[mt][nt][half_*2+1] + bv.y) * sc;
                        *(uint32_t*)(dh + rb + nn) = packh(vx, vy);
                    }
                }
            }
        } else {
            #pragma unroll
            for (int mt = 0; mt < 2; ++mt) {
                #pragma unroll
                for (int half_ = 0; half_ < 2; ++half_) {
                    int m = m0 + wm + mt*16 + mrw + half_*8;
                    int b_ = m >> 11, s_ = m & (SS - 1);
                    size_t base = (size_t)(b_*HH + h) * DD * SS;
                    #pragma unroll
                    for (int nt = 0; nt < 8; ++nt) {
                        int nn = nt*8 + ncl;
                        float2 bv = *(const float2*)(bias + n0 + wn + nn);
                        float vx = acc[mt][nt][half_*2+0] + bv.x;
                        float vy = acc[mt][nt][half_*2+1] + bv.y;
                        g_Vth[base + (size_t)nn     * SS + s_] = __float2half(vx);
                        g_Vth[base + (size_t)(nn+1) * SS + s_] = __float2half(vy);
                    }
                }
            }
        }
    } else {
        #pragma unroll
        for (int mt = 0; mt < 2; ++mt) {
            #pragma unroll
            for (int half_ = 0; half_ < 2; ++half_) {
                int m = m0 + wm + mt*16 + mrw + half_*8;
                float* op = outr + (size_t)m * ND + n0 + wn;
                #pragma unroll
                for (int nt = 0; nt < 8; ++nt) {
                    int nn = nt*8 + ncl;
                    float2 bv = *(const float2*)(bias + n0 + wn + nn);
                    float2 v;
                    v.x = acc[mt][nt][half_*2+0] + bv.x;
                    v.y = acc[mt][nt][half_*2+1] + bv.y;
                    *(float2*)(op + nn) = v;
                }
            }
        }
    }
}

// ---------------------------------------------------------------------------
// fp16 MMA flash attention, static-max softmax. Mask words pipelined one
// k-tile ahead in registers (LDG latency decoupled from the softmax chain).
// ---------------------------------------------------------------------------
#define AROWB 144
#define AQ_B (128*AROWB)        // 18432
#define AK_B (64*AROWB)         // 9216
#define AOFF_KV 18432
#define AKV_STRIDE 18432
#define ATTN_SMEM (AOFF_KV + 3*AKV_STRIDE)   // 73728

__global__ __launch_bounds__(256, 2) void attn_mma_kernel()
{
    extern __shared__ char smc[];
    const uint32_t SB = smem_u32(smc);
    const int t = threadIdx.x, wid = t >> 5, lane = t & 31;
    const int bh = blockIdx.y, b_ = bh >> 4, h = bh & 15;
    const int q0 = blockIdx.x * 128;
    const int wm = wid * 16;

    const __half* Qh = g_Qh + (size_t)bh*SS*DD + (size_t)q0*DD;
    const __half* Kh = g_Kh + (size_t)bh*SS*DD;
    const __half* Vh = g_Vth + (size_t)bh*DD*SS;

    #pragma unroll
    for (int i = 0; i < 4; ++i) {
        int idx = t + i * 256;
        int row = idx >> 3, q = idx & 7;
        cp16(SB + row*AROWB + q*16, Qh + (size_t)row*DD + q*8);
    }
    auto load_kv = [&](int kt, int buf) {
        const int k0 = kt * 64;
        const uint32_t bb = SB + AOFF_KV + buf * AKV_STRIDE;
        #pragma unroll
        for (int i = 0; i < 2; ++i) {
            int idx = t + i * 256;
            int row = idx >> 3, q = idx & 7;
            cp16(bb + row*AROWB + q*16,        Kh + (size_t)(k0+row)*DD + q*8);
            cp16(bb + AK_B + row*AROWB + q*16, Vh + (size_t)row*SS + k0 + q*8);
        }
        cp_commit();
    };
    load_kv(0, 0);
    load_kv(1, 1);
    load_kv(2, 2);

    const int j = lane >> 3, r_ = lane & 7;
    const int rowA = wm + ((j & 1) << 3) + r_;
    const int colA = (j >> 1) << 3;
    const int rowB = ((j >> 1) << 3) + r_;
    const int colB = (j & 1) << 3;
    const int ncl2 = (lane & 3) << 1;
    const int mrw = lane >> 2;

    const uint32_t* mbp[2];
    #pragma unroll
    for (int hf = 0; hf < 2; ++hf)
        mbp[hf] = g_mbits + (size_t)(b_*SS + q0 + wm + hf*8 + mrw) * (SS/32);

    uint32_t aq[4][4];
    cp_wait<2>();
    __syncthreads();
    #pragma unroll
    for (int ks = 0; ks < 4; ++ks)
        ldsm4(aq[ks], SB + (uint32_t)rowA*AROWB + (uint32_t)(colA + ks*16)*2);

    float o[8][4];
    float l_i[2] = {0.0f, 0.0f};
    #pragma unroll
    for (int dn = 0; dn < 8; ++dn)
        #pragma unroll
        for (int q = 0; q < 4; ++q) o[dn][q] = 0.0f;

    // mask-word register pipeline: preload tile 0
    uint32_t mw[2][2];
    mw[0][0] = mbp[0][0]; mw[0][1] = mbp[0][1];
    mw[1][0] = mbp[1][0]; mw[1][1] = mbp[1][1];

    const int NKT = SS/64;
    int buf = 0;
    for (int kt = 0; kt < NKT; ++kt) {
        if (kt == NKT - 1)      cp_wait<0>();
        else if (kt == NKT - 2) cp_wait<1>();
        else                    cp_wait<2>();
        __syncthreads();
        const uint32_t bb = SB + AOFF_KV + buf * AKV_STRIDE;

        // issue next tile's mask loads now; consumed next iteration
        uint32_t mwn[2][2];
        if (kt + 1 < NKT) {
            mwn[0][0] = mbp[0][(kt+1)*2]; mwn[0][1] = mbp[0][(kt+1)*2+1];
            mwn[1][0] = mbp[1][(kt+1)*2]; mwn[1][1] = mbp[1][(kt+1)*2+1];
        }

        // S = Q K^T
        float s[8][4];
        #pragma unroll
        for (int jn = 0; jn < 8; ++jn)
            #pragma unroll
            for (int q = 0; q < 4; ++q) s[jn][q] = 0.0f;

        #pragma unroll
        for (int ks = 0; ks < 4; ++ks) {
            #pragma unroll
            for (int jnp = 0; jnp < 4; ++jnp) {
                uint32_t kh4[4];
                ldsm4(kh4, bb + (uint32_t)(rowB + jnp*16)*AROWB + (uint32_t)(colB + ks*16)*2);
                #pragma unroll
                for (int sub = 0; sub < 2; ++sub) {
                    uint32_t b2[2] = {kh4[sub*2], kh4[sub*2+1]};
                    mma16816(s[jnp*2 + sub], aq[ks], b2);
                }
            }
        }

        // mask -> -inf, p = exp2(s) in fp16 pairs (mask words already resident)
        uint32_t pfrag[8][2];
        #pragma unroll
        for (int jn = 0; jn < 8; ++jn) {
            const int sh = (jn*8 + ncl2) & 31;
            uint32_t w0 = mw[0][jn >> 2] >> sh;
            uint32_t w1 = mw[1][jn >> 2] >> sh;
            float s0 = (w0 & 1u) ? s[jn][0] : -1e30f;
            float s1 = (w0 & 2u) ? s[jn][1] : -1e30f;
            float s2 = (w1 & 1u) ? s[jn][2] : -1e30f;
            float s3 = (w1 & 2u) ? s[jn][3] : -1e30f;
            pfrag[jn][0] = h2ex2(packh(s0, s1));
            pfrag[jn][1] = h2ex2(packh(s2, s3));
        }

        // row-sum on fma pipe (fp32)
        #pragma unroll
        for (int hf = 0; hf < 2; ++hf) {
            float acc = 0.0f;
            #pragma unroll
            for (int jn = 0; jn < 8; ++jn) {
                float2 f = __half22float2(*reinterpret_cast<__half2*>(&pfrag[jn][hf]));
                acc += f.x + f.y;
            }
            acc += __shfl_xor_sync(0xffffffffu, acc, 1);
            acc += __shfl_xor_sync(0xffffffffu, acc, 2);
            l_i[hf] += acc;
        }

        // O += P V
        #pragma unroll
        for (int ks = 0; ks < 4; ++ks) {
            uint32_t pah[4] = {pfrag[2*ks][0], pfrag[2*ks][1],
                               pfrag[2*ks+1][0], pfrag[2*ks+1][1]};
            #pragma unroll
            for (int dnp = 0; dnp < 4; ++dnp) {
                uint32_t vh4[4];
                ldsm4(vh4, bb + AK_B + (uint32_t)(rowB + dnp*16)*AROWB
                           + (uint32_t)(colB + ks*16)*2);
                #pragma unroll
                for (int sub = 0; sub < 2; ++sub) {
                    uint32_t v2[2] = {vh4[sub*2], vh4[sub*2+1]};
                    mma16816(o[dnp*2 + sub], pah, v2);
                }
            }
        }

        // rotate mask pipeline
        mw[0][0] = mwn[0][0]; mw[0][1] = mwn[0][1];
        mw[1][0] = mwn[1][0]; mw[1][1] = mwn[1][1];

        __syncthreads();
        if (kt + 3 < NKT) load_kv(kt + 3, buf);
        buf = (buf == 2) ? 0 : buf + 1;
    }

    #pragma unroll
    for (int hf = 0; hf < 2; ++hf) {
        const int q = q0 + wm + hf*8 + mrw;
        const float inv = 1.0f / l_i[hf];
        size_t base = ((size_t)b_*SS + q) * ND + h*64;
        #pragma unroll
        for (int dn = 0; dn < 8; ++dn) {
            int d0 = dn*8 + ncl2;
            *(uint32_t*)(g_Ah + base + d0) =
                packh(o[dn][hf*2] * inv, o[dn][hf*2+1] * inv);
        }
    }
}

extern "C" void kernel_launch(void* const* d_in, const int* in_sizes, int n_in,
                              void* d_out, int out_size)
{
    const float* X    = (const float*)d_in[0];
    const int*   mask = (const int*)  d_in[1];
    const float* wQ   = (const float*)d_in[2];
    const float* bQ   = (const float*)d_in[3];
    const float* wK   = (const float*)d_in[4];
    const float* bK   = (const float*)d_in[5];
    const float* wV   = (const float*)d_in[6];
    const float* bV   = (const float*)d_in[7];
    const float* wO   = (const float*)d_in[8];
    const float* bO   = (const float*)d_in[9];
    float* out = (float*)d_out;

    cudaFuncSetAttribute(mma_gemm_kernel, cudaFuncAttributeMaxDynamicSharedMemorySize, GSMEM_TOTAL);
    cudaFuncSetAttribute(attn_mma_kernel, cudaFuncAttributeMaxDynamicSharedMemorySize, ATTN_SMEM);

    // fork a side stream so mask packing overlaps the qkv GEMM in the graph
    cudaStream_t s2;
    cudaStreamCreate(&s2);
    cudaEvent_t evFork, evJoin;
    cudaEventCreateWithFlags(&evFork, cudaEventDisableTiming);
    cudaEventCreateWithFlags(&evJoin, cudaEventDisableTiming);

    prep_kernel<<<PREP_BLOCKS, 256>>>(X, wQ, wK, wV, wO);

    cudaEventRecord(evFork, 0);
    cudaStreamWaitEvent(s2, evFork, 0);
    pack_mask_kernel<<<2048, 256, 0, s2>>>(mask);      // overlaps with qkv below
    cudaEventRecord(evJoin, s2);

    mma_gemm_kernel<<<dim3(8, 64, 3), 256, GSMEM_TOTAL>>>(0, bQ, bK, bV, 1, nullptr);

    cudaStreamWaitEvent(0, evJoin, 0);                 // attention needs the bitmask
    attn_mma_kernel<<<dim3(16, 64), 256, ATTN_SMEM>>>();
    mma_gemm_kernel<<<dim3(8, 64, 1), 256, GSMEM_TOTAL>>>(3, bO, bO, bO, 0, out);

    cudaEventDestroy(evFork);
    cudaEventDestroy(evJoin);
    cudaStreamDestroy(s2);
}